// round 11
// baseline (speedup 1.0000x reference)
#include <cuda_runtime.h>
#include <math.h>

#define Bb 2
#define Nn 1000
#define KNN 8
#define FEAT 672
#define DPAIR 128

// ---------------- scratch (device globals; no allocation) ----------------
__device__ int   d_knn[Bb * Nn * KNN];
__device__ float d_feat[Bb * Nn * FEAT];    // x1 | x2 | x3 packed at cols 0,32,160
__device__ float d_sf[Bb * Nn * DPAIR];
__device__ float d_gp[Bb * 8 * DPAIR];
__device__ float d_g[Bb * DPAIR];
__device__ float d_hi[Bb * Nn * DPAIR];
__device__ float d_hj[Bb * Nn * DPAIR];
__device__ float d_hg[Bb * DPAIR];

// ---------------- f32x2 packed helpers ----------------
__device__ __forceinline__ unsigned long long pack2(float v) {
    unsigned long long r;
    asm("mov.b64 %0, {%1, %1};" : "=l"(r) : "f"(v));
    return r;
}
__device__ __forceinline__ unsigned long long packab(float a, float b) {
    unsigned long long r;
    asm("mov.b64 %0, {%1, %2};" : "=l"(r) : "f"(a), "f"(b));
    return r;
}
#define FFMA2(acc, a, b) asm("fma.rn.f32x2 %0, %1, %2, %0;" : "+l"(acc) : "l"(a), "l"(b))
__device__ __forceinline__ void unpk(unsigned long long v, float& lo, float& hi) {
    asm("mov.b64 {%0, %1}, %2;" : "=f"(lo), "=f"(hi) : "l"(v));
}
__device__ __forceinline__ float hsum2(unsigned long long v) {
    float lo, hi; unpk(v, lo, hi); return lo + hi;
}

// ---------------- kNN batched: 8 points per CTA ----------------
template <int C>
__global__ __launch_bounds__(256) void knn_b(const float* __restrict__ x, int ld, int off) {
    __shared__ float sd2[8][Nn];
    __shared__ float sxi[8][C];
    int t  = threadIdx.x;
    int p0 = blockIdx.x * 8;
    int b  = p0 / Nn;
    for (int idx = t; idx < 8 * C; idx += 256)
        sxi[idx / C][idx % C] = x[(size_t)(p0 + idx / C) * ld + off + (idx % C)];
    __syncthreads();
    const float* xb = x + (size_t)b * Nn * ld + off;
    for (int j = t; j < Nn; j += 256) {
        if (C % 4 == 0) {
            const float4* xp = (const float4*)(xb + (size_t)j * ld);
            unsigned long long acc[8], nrm = 0ull;
            #pragma unroll
            for (int r = 0; r < 8; r++) acc[r] = 0ull;
            #pragma unroll
            for (int c4 = 0; c4 < C / 4; c4++) {
                float4 v = xp[c4];
                unsigned long long v01 = packab(v.x, v.y);
                unsigned long long v23 = packab(v.z, v.w);
                FFMA2(nrm, v01, v01);
                FFMA2(nrm, v23, v23);
                #pragma unroll
                for (int r = 0; r < 8; r++) {
                    const unsigned long long* s = (const unsigned long long*)(sxi[r]);
                    FFMA2(acc[r], v01, s[2 * c4]);
                    FFMA2(acc[r], v23, s[2 * c4 + 1]);
                }
            }
            float sqj = hsum2(nrm);
            #pragma unroll
            for (int r = 0; r < 8; r++)
                sd2[r][j] = fmaf(-2.f, hsum2(acc[r]), sqj);   // sq_i constant per row: dropped
        } else {
            const float* xj = xb + (size_t)j * ld;
            float v0 = xj[0], v1 = xj[1], v2 = xj[2];
            float sqj = v0 * v0 + v1 * v1 + v2 * v2;
            #pragma unroll
            for (int r = 0; r < 8; r++) {
                float dot = sxi[r][0] * v0 + sxi[r][1] * v1 + sxi[r][2] * v2;
                sd2[r][j] = fmaf(-2.f, dot, sqj);
            }
        }
    }
    __syncthreads();
    int w = t >> 5, lane = t & 31;
    float* row = sd2[w];
    for (int k = 0; k < KNN; k++) {
        float bv = 3.4e38f; int bi = Nn;
        for (int j = lane; j < Nn; j += 32) {
            float v = row[j];
            if (v < bv) { bv = v; bi = j; }
        }
        #pragma unroll
        for (int o = 16; o > 0; o >>= 1) {
            float ov = __shfl_down_sync(0xffffffffu, bv, o);
            int   oi = __shfl_down_sync(0xffffffffu, bi, o);
            if (ov < bv || (ov == bv && oi < bi)) { bv = ov; bi = oi; }
        }
        bi = __shfl_sync(0xffffffffu, bi, 0);
        if (lane == 0) { d_knn[(p0 + w) * KNN + k] = bi; row[bi] = 3.4e38f; }
        __syncwarp();
    }
}

// ---------------- f32x2 GEMM tile, TM=4 rows per thread ----------------
template <int KK, int NC, int MP, int NT>
__device__ __forceinline__ void gemm_t4(
    const float* __restrict__ At, const float* __restrict__ Wg, int ldw, int col0,
    float* __restrict__ Wt, unsigned long long (&acc)[4][4], int tx, int ty, int t)
{
    constexpr int P2 = NC / 64;
    for (int kb = 0; kb < KK; kb += 32) {
        for (int idx = t; idx < 32 * (NC / 4); idx += NT) {
            int c  = idx / (NC / 4);
            int u4 = idx - c * (NC / 4);
            ((float4*)Wt)[idx] = *(const float4*)(Wg + (size_t)(kb + c) * ldw + col0 + u4 * 4);
        }
        __syncthreads();
        #pragma unroll 4
        for (int c = 0; c < 32; c++) {
            float4 a0 = *(const float4*)(At + (kb + c) * MP + ty * 4);
            unsigned long long e0 = pack2(a0.x), e1 = pack2(a0.y);
            unsigned long long e2 = pack2(a0.z), e3 = pack2(a0.w);
            const unsigned long long* wrow = (const unsigned long long*)(Wt + c * NC);
            #pragma unroll
            for (int p = 0; p < P2; p++) {
                unsigned long long wv = wrow[tx + p * 32];
                FFMA2(acc[0][p], e0, wv);
                FFMA2(acc[1][p], e1, wv);
                FFMA2(acc[2][p], e2, wv);
                FFMA2(acc[3][p], e3, wv);
            }
        }
        __syncthreads();
    }
}

// ---------------- EdgeConv: PTS points (PTS*8 edges) per CTA, NT threads ----
template <int CIN, int H, int COUT, int PTS, int NT>
__global__ __launch_bounds__(NT) void edgeconv_g(
    const float* __restrict__ x, int ld, int off, int off_out,
    const float* __restrict__ w1, const float* __restrict__ b1,
    const float* __restrict__ w2, const float* __restrict__ b2)
{
    constexpr int ED  = PTS * 8;
    constexpr int MP  = ED + 4;
    constexpr int K1  = 2 * CIN;
    constexpr int NC1 = H;
    constexpr int NC2 = (COUT > 256) ? 256 : COUT;
    extern __shared__ float sm[];
    float* sxi = sm;                      // PTS*CIN
    float* Et  = sxi + PTS * CIN;         // K1*MP
    float* Ht  = Et + K1 * MP;            // H*MP
    float* Wt  = Ht + H * MP;             // 32*max(NC1,NC2) floats (also pmax buffer)
    __shared__ int sidx[ED];
    int t = threadIdx.x, tx = t & 31, ty = t >> 5;
    int p0 = blockIdx.x * PTS;
    int b  = p0 / Nn;
    if (t < ED) sidx[t] = d_knn[p0 * KNN + t];
    for (int idx = t; idx < PTS * CIN; idx += NT)
        sxi[idx] = x[(size_t)(p0 + idx / CIN) * ld + off + (idx % CIN)];
    __syncthreads();
    // E^T[2CIN][ED]
    for (int idx = t; idx < ED * (CIN / 4); idx += NT) {
        int r = idx & (ED - 1), c4 = idx / ED;
        float4 v = *(const float4*)(x + ((size_t)b * Nn + sidx[r]) * ld + off + c4 * 4);
        const float* xi = sxi + (r >> 3) * CIN + c4 * 4;
        float i0 = xi[0], i1 = xi[1], i2 = xi[2], i3 = xi[3];
        Et[(c4 * 4 + 0) * MP + r] = i0;
        Et[(c4 * 4 + 1) * MP + r] = i1;
        Et[(c4 * 4 + 2) * MP + r] = i2;
        Et[(c4 * 4 + 3) * MP + r] = i3;
        Et[(CIN + c4 * 4 + 0) * MP + r] = v.x - i0;
        Et[(CIN + c4 * 4 + 1) * MP + r] = v.y - i1;
        Et[(CIN + c4 * 4 + 2) * MP + r] = v.z - i2;
        Et[(CIN + c4 * 4 + 3) * MP + r] = v.w - i3;
    }
    __syncthreads();
    // GEMM1: Ht = relu(E*W1 + b1)
    unsigned long long acc[4][4];
    #pragma unroll
    for (int m = 0; m < 4; m++)
        #pragma unroll
        for (int p = 0; p < 4; p++) acc[m][p] = 0ull;
    gemm_t4<K1, NC1, MP, NT>(Et, w1, H, 0, Wt, acc, tx, ty, t);
    constexpr int P1 = NC1 / 64;
    #pragma unroll
    for (int p = 0; p < P1; p++) {
        int u0 = tx * 2 + p * 64;
        float bb0 = b1[u0], bb1 = b1[u0 + 1];
        #pragma unroll
        for (int m = 0; m < 4; m++) {
            float lo, hi; unpk(acc[m][p], lo, hi);
            Ht[u0 * MP + ty * 4 + m]       = fmaxf(lo + bb0, 0.f);
            Ht[(u0 + 1) * MP + ty * 4 + m] = fmaxf(hi + bb1, 0.f);
        }
    }
    __syncthreads();
    // GEMM2 + max over 8 neighbors (rows of point p span row-groups 2p, 2p+1)
    for (int col0 = 0; col0 < COUT; col0 += NC2) {
        #pragma unroll
        for (int m = 0; m < 4; m++)
            #pragma unroll
            for (int p = 0; p < 4; p++) acc[m][p] = 0ull;
        gemm_t4<H, NC2, MP, NT>(Ht, w2, COUT, col0, Wt, acc, tx, ty, t);
        float* pmax = Wt;   // free after gemm's trailing sync
        constexpr int P2c = NC2 / 64;
        #pragma unroll
        for (int p = 0; p < P2c; p++) {
            int u0 = tx * 2 + p * 64;
            float m0 = -3.4e38f, m1 = -3.4e38f;
            #pragma unroll
            for (int m = 0; m < 4; m++) {
                float lo, hi; unpk(acc[m][p], lo, hi);
                m0 = fmaxf(m0, lo);
                m1 = fmaxf(m1, hi);
            }
            pmax[ty * NC2 + u0]     = m0;
            pmax[ty * NC2 + u0 + 1] = m1;
        }
        __syncthreads();
        for (int idx = t; idx < PTS * NC2; idx += NT) {
            int pp = idx / NC2, c = idx % NC2;
            float v = fmaxf(pmax[(2 * pp) * NC2 + c], pmax[(2 * pp + 1) * NC2 + c]) + b2[col0 + c];
            d_feat[(size_t)(p0 + pp) * FEAT + off_out + col0 + c] = v;
        }
        __syncthreads();
    }
}

// ---------------- EdgeConv stage 1 (3->6->16->32), parallel over (k,u)/(k,o) --
__global__ __launch_bounds__(256) void edgeconv1(
    const float* __restrict__ x,
    const float* __restrict__ w1, const float* __restrict__ b1,
    const float* __restrict__ w2, const float* __restrict__ b2)
{
    __shared__ float se[KNN][8];
    __shared__ float sh[KNN][16];
    __shared__ float sp[KNN][32];
    __shared__ float sxi[3];
    __shared__ int   sidx[KNN];
    int row = blockIdx.x;
    int b   = row / Nn;
    int t   = threadIdx.x;
    if (t < 3) sxi[t] = x[(size_t)row * 3 + t];
    if (t < KNN) sidx[t] = d_knn[row * KNN + t];
    __syncthreads();
    if (t < 24) {
        int k = t / 3, c = t % 3;
        float xj = x[((size_t)b * Nn + sidx[k]) * 3 + c];
        se[k][c]     = sxi[c];
        se[k][3 + c] = xj - sxi[c];
    }
    __syncthreads();
    if (t < 128) {
        int u = t & 15, k = t >> 4;
        float a = b1[u];
        #pragma unroll
        for (int c = 0; c < 6; c++) a += se[k][c] * w1[c * 16 + u];
        sh[k][u] = a > 0.f ? a : 0.f;
    }
    __syncthreads();
    {
        int o = t & 31, k = t >> 5;
        float a = 0.f;
        #pragma unroll
        for (int u = 0; u < 16; u++) a += sh[k][u] * w2[u * 32 + o];
        sp[k][o] = a;
    }
    __syncthreads();
    if (t < 32) {
        float m = sp[0][t];
        #pragma unroll
        for (int k = 1; k < KNN; k++) m = fmaxf(m, sp[k][t]);
        d_feat[(size_t)row * FEAT + t] = m + b2[t];
    }
}

// ---------------- sf-MLP batched: 16 points per CTA ----------------
template <int KK, int NC, int TM, int MP>
__device__ __forceinline__ void gemm_f2(
    const float* __restrict__ At, const float* __restrict__ Wg, int ldw, int col0,
    float* __restrict__ Wt, unsigned long long (&acc)[TM][4], int tx, int ty, int t)
{
    constexpr int P2 = NC / 64;
    for (int kb = 0; kb < KK; kb += 32) {
        for (int idx = t; idx < 32 * (NC / 4); idx += 256) {
            int c  = idx / (NC / 4);
            int u4 = idx - c * (NC / 4);
            ((float4*)Wt)[idx] = *(const float4*)(Wg + (size_t)(kb + c) * ldw + col0 + u4 * 4);
        }
        __syncthreads();
        #pragma unroll 4
        for (int c = 0; c < 32; c++) {
            const float* arow = At + (kb + c) * MP + ty * TM;
            float2 a = *(const float2*)(arow);
            unsigned long long ep0 = pack2(a.x), ep1 = pack2(a.y);
            const unsigned long long* wrow = (const unsigned long long*)(Wt + c * NC);
            #pragma unroll
            for (int p = 0; p < P2; p++) {
                unsigned long long wv = wrow[tx + p * 32];
                FFMA2(acc[0][p], ep0, wv);
                FFMA2(acc[1 % TM][p], ep1, wv);
            }
        }
        __syncthreads();
    }
}

__global__ __launch_bounds__(256) void sfmlp_b(
    const float* __restrict__ w1, const float* __restrict__ b1,
    const float* __restrict__ w2, const float* __restrict__ b2)
{
    constexpr int MP = 20;
    extern __shared__ float sm[];
    float* Xt = sm;
    float* Ht = Xt + FEAT * MP;
    float* Wt = Ht + 256 * MP;
    int t = threadIdx.x, tx = t & 31, ty = t >> 5;
    int p0 = blockIdx.x * 16;
    for (int idx = t; idx < 16 * (FEAT / 4); idx += 256) {
        int r = idx & 15, c4 = idx >> 4;
        float4 v = *(const float4*)(d_feat + (size_t)(p0 + r) * FEAT + c4 * 4);
        Xt[(c4 * 4 + 0) * MP + r] = v.x;
        Xt[(c4 * 4 + 1) * MP + r] = v.y;
        Xt[(c4 * 4 + 2) * MP + r] = v.z;
        Xt[(c4 * 4 + 3) * MP + r] = v.w;
    }
    __syncthreads();
    unsigned long long acc[2][4];
    #pragma unroll
    for (int m = 0; m < 2; m++)
        #pragma unroll
        for (int p = 0; p < 4; p++) acc[m][p] = 0ull;
    gemm_f2<FEAT, 256, 2, MP>(Xt, w1, 256, 0, Wt, acc, tx, ty, t);
    #pragma unroll
    for (int p = 0; p < 4; p++) {
        int u0 = tx * 2 + p * 64;
        float bb0 = b1[u0], bb1 = b1[u0 + 1];
        #pragma unroll
        for (int m = 0; m < 2; m++) {
            float lo, hi; unpk(acc[m][p], lo, hi);
            Ht[u0 * MP + ty * 2 + m]       = fmaxf(lo + bb0, 0.f);
            Ht[(u0 + 1) * MP + ty * 2 + m] = fmaxf(hi + bb1, 0.f);
        }
    }
    __syncthreads();
    #pragma unroll
    for (int m = 0; m < 2; m++)
        #pragma unroll
        for (int p = 0; p < 4; p++) acc[m][p] = 0ull;
    gemm_f2<256, 128, 2, MP>(Ht, w2, 128, 0, Wt, acc, tx, ty, t);
    #pragma unroll
    for (int p = 0; p < 2; p++) {
        int u0 = tx * 2 + p * 64;
        float bb0 = b2[u0], bb1 = b2[u0 + 1];
        #pragma unroll
        for (int m = 0; m < 2; m++) {
            float lo, hi; unpk(acc[m][p], lo, hi);
            float* o = d_sf + (size_t)(p0 + ty * 2 + m) * 128 + u0;
            o[0] = lo + bb0; o[1] = hi + bb1;
        }
    }
}

// ---------------- global max pool: partial + final ----------------
__global__ void gmax_part() {
    int b = blockIdx.x, s = blockIdx.y, o = threadIdx.x;
    const float* p = d_sf + ((size_t)b * Nn + s * 125) * 128 + o;
    float m0 = -3.4e38f, m1 = -3.4e38f, m2 = -3.4e38f, m3 = -3.4e38f;
    for (int n = 0; n < 124; n += 4) {
        m0 = fmaxf(m0, p[(n + 0) * 128]);
        m1 = fmaxf(m1, p[(n + 1) * 128]);
        m2 = fmaxf(m2, p[(n + 2) * 128]);
        m3 = fmaxf(m3, p[(n + 3) * 128]);
    }
    m0 = fmaxf(m0, p[124 * 128]);
    d_gp[(b * 8 + s) * 128 + o] = fmaxf(fmaxf(m0, m1), fmaxf(m2, m3));
}
__global__ void gmax_fin() {
    int t = threadIdx.x;
    int b = t >> 7, o = t & 127;
    float m = -3.4e38f;
    #pragma unroll
    for (int s = 0; s < 8; s++) m = fmaxf(m, d_gp[(b * 8 + s) * 128 + o]);
    d_g[b * 128 + o] = m;
}

// ---------------- hi/hj projection: 8 points per CTA ----------------
__global__ __launch_bounds__(256) void hij_b(const float* __restrict__ ecw1) {
    __shared__ float st[128][10];
    int t = threadIdx.x;
    int p0 = blockIdx.x * 8;
    for (int idx = t; idx < 8 * 128; idx += 256) {
        int r = idx >> 7, d = idx & 127;
        st[d][r] = d_sf[(size_t)(p0 + r) * 128 + d];
    }
    __syncthreads();
    int col = t & 127, which = t >> 7;
    const float* w = ecw1 + (size_t)which * 128 * 128 + col;
    unsigned long long acc[4] = {0ull, 0ull, 0ull, 0ull};
    for (int d = 0; d < 128; d++) {
        unsigned long long wv = pack2(w[(size_t)d * 128]);
        const unsigned long long* sp = (const unsigned long long*)(&st[d][0]);
        #pragma unroll
        for (int m = 0; m < 4; m++) FFMA2(acc[m], sp[m], wv);
    }
    float* out = which ? d_hj : d_hi;
    #pragma unroll
    for (int m = 0; m < 4; m++) {
        float lo, hi; unpk(acc[m], lo, hi);
        out[(size_t)(p0 + 2 * m) * 128 + col]     = lo;
        out[(size_t)(p0 + 2 * m + 1) * 128 + col] = hi;
    }
}

// ---------------- hg = g @ W[256:] + b1 ----------------
__global__ void hg_kernel(const float* __restrict__ ecw1, const float* __restrict__ ecb1) {
    int t = threadIdx.x;
    int b = t >> 7, o = t & 127;
    float acc = ecb1[o];
    for (int d = 0; d < 128; d++) acc += d_g[b * 128 + d] * ecw1[(256 + d) * 128 + o];
    d_hg[b * 128 + o] = acc;
}

// ---------------- pair scorer: 32x32 tiles, 2x2 register tiling ----------------
#define TILE 32
#define PADC 132
__global__ __launch_bounds__(256) void pair_kernel(
    const float* __restrict__ ecw2, const float* __restrict__ ecb2,
    float* __restrict__ out, int write_logits)
{
    __shared__ __align__(16) float shi[TILE][PADC];
    __shared__ __align__(16) float shj[TILE][PADC];
    __shared__ __align__(16) float shg[128];
    __shared__ __align__(16) float sw2[128];
    int jt = blockIdx.x, it = blockIdx.y, b = blockIdx.z;
    if (jt < it) return;
    int t  = threadIdx.x;
    int i0 = it * TILE, j0 = jt * TILE;
    if (t < 128) { shg[t] = d_hg[b * 128 + t]; sw2[t] = ecw2[t]; }
    __syncthreads();
    for (int idx = t; idx < TILE * 128; idx += 256) {
        int r = idx >> 7, u = idx & 127;
        int gi = i0 + r, gj = j0 + r;
        shi[r][u] = (gi < Nn) ? d_hi[((size_t)b * Nn + gi) * 128 + u] + shg[u] : 0.f;
        shj[r][u] = (gj < Nn) ? d_hj[((size_t)b * Nn + gj) * 128 + u] : 0.f;
    }
    __syncthreads();
    float bias = ecb2[0];
    const long P = (long)Nn * (Nn - 1) / 2;
    int ii = t >> 4;       // 0..15 -> rows ii, ii+16
    int jj = t & 15;       // 0..15 -> rows jj, jj+16
    float a00 = 0.f, a01 = 0.f, a10 = 0.f, a11 = 0.f;
    const float4* vi0 = (const float4*)shi[ii];
    const float4* vi1 = (const float4*)shi[ii + 16];
    const float4* vj0 = (const float4*)shj[jj];
    const float4* vj1 = (const float4*)shj[jj + 16];
    const float4* vw  = (const float4*)sw2;
    #pragma unroll
    for (int q = 0; q < 32; q++) {
        float4 A0 = vi0[q], A1 = vi1[q], B0 = vj0[q], B1 = vj1[q], w = vw[q];
        a00 += fmaxf(A0.x + B0.x, 0.f) * w.x; a00 += fmaxf(A0.y + B0.y, 0.f) * w.y;
        a00 += fmaxf(A0.z + B0.z, 0.f) * w.z; a00 += fmaxf(A0.w + B0.w, 0.f) * w.w;
        a01 += fmaxf(A0.x + B1.x, 0.f) * w.x; a01 += fmaxf(A0.y + B1.y, 0.f) * w.y;
        a01 += fmaxf(A0.z + B1.z, 0.f) * w.z; a01 += fmaxf(A0.w + B1.w, 0.f) * w.w;
        a10 += fmaxf(A1.x + B0.x, 0.f) * w.x; a10 += fmaxf(A1.y + B0.y, 0.f) * w.y;
        a10 += fmaxf(A1.z + B0.z, 0.f) * w.z; a10 += fmaxf(A1.w + B0.w, 0.f) * w.w;
        a11 += fmaxf(A1.x + B1.x, 0.f) * w.x; a11 += fmaxf(A1.y + B1.y, 0.f) * w.y;
        a11 += fmaxf(A1.z + B1.z, 0.f) * w.z; a11 += fmaxf(A1.w + B1.w, 0.f) * w.w;
    }
    float accs[2][2] = {{a00, a01}, {a10, a11}};
    #pragma unroll
    for (int a = 0; a < 2; a++) {
        #pragma unroll
        for (int c = 0; c < 2; c++) {
            int i = i0 + ii + a * 16;
            int j = j0 + jj + c * 16;
            if (i < Nn && j < Nn && i < j) {
                float logit = accs[a][c] + bias;
                long pidx = (long)b * P + (long)i * (2 * Nn - i - 1) / 2 + (j - i - 1);
                out[pidx] = 1.f / (1.f + __expf(-logit));
                if (write_logits) out[(long)Bb * P + pidx] = logit;
            }
        }
    }
}

extern "C" void kernel_launch(void* const* d_in, const int* in_sizes, int n_in,
                              void* d_out, int out_size) {
    const float* pos  = (const float*)d_in[0];
    const float* c1w1 = (const float*)d_in[1];
    const float* c1b1 = (const float*)d_in[2];
    const float* c1w2 = (const float*)d_in[3];
    const float* c1b2 = (const float*)d_in[4];
    const float* c2w1 = (const float*)d_in[5];
    const float* c2b1 = (const float*)d_in[6];
    const float* c2w2 = (const float*)d_in[7];
    const float* c2b2 = (const float*)d_in[8];
    const float* c3w1 = (const float*)d_in[9];
    const float* c3b1 = (const float*)d_in[10];
    const float* c3w2 = (const float*)d_in[11];
    const float* c3b2 = (const float*)d_in[12];
    const float* smw1 = (const float*)d_in[13];
    const float* smb1 = (const float*)d_in[14];
    const float* smw2 = (const float*)d_in[15];
    const float* smb2 = (const float*)d_in[16];
    const float* ecw1 = (const float*)d_in[17];
    const float* ecb1 = (const float*)d_in[18];
    const float* ecw2 = (const float*)d_in[19];
    const float* ecb2 = (const float*)d_in[20];
    float* out = (float*)d_out;

    const long P = (long)Nn * (Nn - 1) / 2;
    int write_logits = ((long)out_size >= 2L * Bb * P) ? 1 : 0;

    float* feat = nullptr;
    cudaGetSymbolAddress((void**)&feat, d_feat);

    // dynamic smem: sxi + Et + Ht + Wt (floats)
    const int SM2 = (4 * 32 + 64 * 36 + 64 * 36 + 32 * 128) * 4;       // 35,328 B
    const int SM3 = (8 * 128 + 256 * 68 + 256 * 68 + 32 * 256) * 4;    // 176,128 B
    const int SMS = (FEAT * 20 + 256 * 20 + 32 * 256) * 4;             // 107,008 B
    cudaFuncSetAttribute(edgeconv_g<32, 64, 128, 4, 256>,   cudaFuncAttributeMaxDynamicSharedMemorySize, SM2);
    cudaFuncSetAttribute(edgeconv_g<128, 256, 512, 8, 512>, cudaFuncAttributeMaxDynamicSharedMemorySize, SM3);
    cudaFuncSetAttribute(sfmlp_b, cudaFuncAttributeMaxDynamicSharedMemorySize, SMS);

    // stage 1: kNN on pos (C=3), EdgeConv 6->16->32 -> feat[:,0:32]
    knn_b<3><<<250, 256>>>(pos, 3, 0);
    edgeconv1<<<Bb * Nn, 256>>>(pos, c1w1, c1b1, c1w2, c1b2);

    // stage 2: kNN on x1 (C=32), EdgeConv 64->64->128 -> feat[:,32:160]
    knn_b<32><<<250, 256>>>(feat, FEAT, 0);
    edgeconv_g<32, 64, 128, 4, 256><<<500, 256, SM2>>>(feat, FEAT, 0, 32, c2w1, c2b1, c2w2, c2b2);

    // stage 3: kNN on x2 (C=128), EdgeConv 256->256->512 -> feat[:,160:672]
    knn_b<128><<<250, 256>>>(feat, FEAT, 32);
    edgeconv_g<128, 256, 512, 8, 512><<<250, 512, SM3>>>(feat, FEAT, 32, 160, c3w1, c3b1, c3w2, c3b2);

    // sf MLP, global max, pair projections
    sfmlp_b<<<125, 256, SMS>>>(smw1, smb1, smw2, smb2);
    dim3 gg(Bb, 8);
    gmax_part<<<gg, 128>>>();
    gmax_fin<<<1, 256>>>();
    hij_b<<<250, 256>>>(ecw1);
    hg_kernel<<<1, 256>>>(ecw1, ecb1);

    // pair scorer
    dim3 pg((Nn + TILE - 1) / TILE, (Nn + TILE - 1) / TILE, Bb);
    pair_kernel<<<pg, 256>>>(ecw2, ecb2, out, write_logits);
}

// round 12
// speedup vs baseline: 1.0231x; 1.0231x over previous
#include <cuda_runtime.h>
#include <math.h>

#define Bb 2
#define Nn 1000
#define KNN 8
#define FEAT 672
#define DPAIR 128

// ---------------- scratch (device globals; no allocation) ----------------
__device__ int   d_knn[Bb * Nn * KNN];
__device__ float d_feat[Bb * Nn * FEAT];    // x1 | x2 | x3 packed at cols 0,32,160
__device__ float d_sf[Bb * Nn * DPAIR];
__device__ float d_gp[Bb * 8 * DPAIR];
__device__ float d_g[Bb * DPAIR];
__device__ float d_hi[Bb * Nn * DPAIR];
__device__ float d_hj[Bb * Nn * DPAIR];
__device__ float d_hg[Bb * DPAIR];

// ---------------- f32x2 packed helpers ----------------
__device__ __forceinline__ unsigned long long pack2(float v) {
    unsigned long long r;
    asm("mov.b64 %0, {%1, %1};" : "=l"(r) : "f"(v));
    return r;
}
__device__ __forceinline__ unsigned long long packab(float a, float b) {
    unsigned long long r;
    asm("mov.b64 %0, {%1, %2};" : "=l"(r) : "f"(a), "f"(b));
    return r;
}
#define FFMA2(acc, a, b) asm("fma.rn.f32x2 %0, %1, %2, %0;" : "+l"(acc) : "l"(a), "l"(b))
__device__ __forceinline__ void unpk(unsigned long long v, float& lo, float& hi) {
    asm("mov.b64 {%0, %1}, %2;" : "=f"(lo), "=f"(hi) : "l"(v));
}
__device__ __forceinline__ float hsum2(unsigned long long v) {
    float lo, hi; unpk(v, lo, hi); return lo + hi;
}

// ---------------- kNN batched: 8 points per CTA ----------------
template <int C>
__global__ __launch_bounds__(256) void knn_b(const float* __restrict__ x, int ld, int off) {
    __shared__ float sd2[8][Nn];
    __shared__ float sxi[8][C];
    int t  = threadIdx.x;
    int p0 = blockIdx.x * 8;
    int b  = p0 / Nn;
    for (int idx = t; idx < 8 * C; idx += 256)
        sxi[idx / C][idx % C] = x[(size_t)(p0 + idx / C) * ld + off + (idx % C)];
    __syncthreads();
    const float* xb = x + (size_t)b * Nn * ld + off;
    for (int j = t; j < Nn; j += 256) {
        if (C % 4 == 0) {
            const float4* xp = (const float4*)(xb + (size_t)j * ld);
            unsigned long long acc[8], nrm = 0ull;
            #pragma unroll
            for (int r = 0; r < 8; r++) acc[r] = 0ull;
            #pragma unroll
            for (int c4 = 0; c4 < C / 4; c4++) {
                float4 v = xp[c4];
                unsigned long long v01 = packab(v.x, v.y);
                unsigned long long v23 = packab(v.z, v.w);
                FFMA2(nrm, v01, v01);
                FFMA2(nrm, v23, v23);
                #pragma unroll
                for (int r = 0; r < 8; r++) {
                    const unsigned long long* s = (const unsigned long long*)(sxi[r]);
                    FFMA2(acc[r], v01, s[2 * c4]);
                    FFMA2(acc[r], v23, s[2 * c4 + 1]);
                }
            }
            float sqj = hsum2(nrm);
            #pragma unroll
            for (int r = 0; r < 8; r++)
                sd2[r][j] = fmaf(-2.f, hsum2(acc[r]), sqj);   // sq_i constant per row: dropped
        } else {
            const float* xj = xb + (size_t)j * ld;
            float v0 = xj[0], v1 = xj[1], v2 = xj[2];
            float sqj = v0 * v0 + v1 * v1 + v2 * v2;
            #pragma unroll
            for (int r = 0; r < 8; r++) {
                float dot = sxi[r][0] * v0 + sxi[r][1] * v1 + sxi[r][2] * v2;
                sd2[r][j] = fmaf(-2.f, dot, sqj);
            }
        }
    }
    __syncthreads();
    int w = t >> 5, lane = t & 31;
    float* row = sd2[w];
    for (int k = 0; k < KNN; k++) {
        float bv = 3.4e38f; int bi = Nn;
        for (int j = lane; j < Nn; j += 32) {
            float v = row[j];
            if (v < bv) { bv = v; bi = j; }
        }
        #pragma unroll
        for (int o = 16; o > 0; o >>= 1) {
            float ov = __shfl_down_sync(0xffffffffu, bv, o);
            int   oi = __shfl_down_sync(0xffffffffu, bi, o);
            if (ov < bv || (ov == bv && oi < bi)) { bv = ov; bi = oi; }
        }
        bi = __shfl_sync(0xffffffffu, bi, 0);
        if (lane == 0) { d_knn[(p0 + w) * KNN + k] = bi; row[bi] = 3.4e38f; }
        __syncwarp();
    }
}

// ---------------- f32x2 GEMM, TM=8 rows per thread (rows = one point's edges) --
// At: shared [KK][MP] transposed; Wg: global row-major [*, ldw].
// Thread layout: warp w -> rg = w/CG (8 rows rg*8..rg*8+7), cg = w%CG.
// Thread covers cols (u64 units): cg*(NC/CG/2) + tx + p*32, p < PP.
template <int KK, int NC, int MP, int NT, int CG, int PP>
__device__ __forceinline__ void gemm_t8(
    const float* __restrict__ At, const float* __restrict__ Wg, int ldw, int col0,
    float* __restrict__ Wt, unsigned long long (&acc)[8][2], int tx, int rg, int cg, int t)
{
    for (int kb = 0; kb < KK; kb += 32) {
        for (int idx = t; idx < 32 * (NC / 4); idx += NT) {
            int c  = idx / (NC / 4);
            int u4 = idx - c * (NC / 4);
            ((float4*)Wt)[idx] = *(const float4*)(Wg + (size_t)(kb + c) * ldw + col0 + u4 * 4);
        }
        __syncthreads();
        #pragma unroll 4
        for (int c = 0; c < 32; c++) {
            const float* ar = At + (kb + c) * MP + rg * 8;
            float4 a0 = *(const float4*)ar;            // broadcast (all lanes same addr)
            float4 a1 = *(const float4*)(ar + 4);
            unsigned long long e0 = pack2(a0.x), e1 = pack2(a0.y);
            unsigned long long e2 = pack2(a0.z), e3 = pack2(a0.w);
            unsigned long long e4 = pack2(a1.x), e5 = pack2(a1.y);
            unsigned long long e6 = pack2(a1.z), e7 = pack2(a1.w);
            const unsigned long long* wr =
                (const unsigned long long*)(Wt + c * NC) + cg * (NC / CG / 2);
            #pragma unroll
            for (int p = 0; p < PP; p++) {
                unsigned long long wv = wr[tx + p * 32];
                FFMA2(acc[0][p], e0, wv);
                FFMA2(acc[1][p], e1, wv);
                FFMA2(acc[2][p], e2, wv);
                FFMA2(acc[3][p], e3, wv);
                FFMA2(acc[4][p], e4, wv);
                FFMA2(acc[5][p], e5, wv);
                FFMA2(acc[6][p], e6, wv);
                FFMA2(acc[7][p], e7, wv);
            }
        }
        __syncthreads();
    }
}

// ---------------- EdgeConv: 8 points (64 edges) per CTA, TM=8 -----------------
template <int CIN, int H, int COUT, int NT, int CG>
__global__ __launch_bounds__(NT) void edgeconv8(
    const float* __restrict__ x, int ld, int off, int off_out,
    const float* __restrict__ w1, const float* __restrict__ b1,
    const float* __restrict__ w2, const float* __restrict__ b2)
{
    constexpr int ED  = 64;
    constexpr int MP  = 68;
    constexpr int K1  = 2 * CIN;
    constexpr int NC1 = H;
    constexpr int NC2 = (COUT > 256) ? 256 : COUT;
    constexpr int PP1 = NC1 / CG / 64;
    constexpr int PP2 = NC2 / CG / 64;
    extern __shared__ float sm[];
    float* sxi = sm;                      // 8*CIN
    float* Et  = sxi + 8 * CIN;           // K1*MP
    float* Ht  = Et + K1 * MP;            // H*MP
    float* Wt  = Ht + H * MP;             // 32*max(NC1,NC2)
    __shared__ int sidx[ED];
    int t = threadIdx.x, tx = t & 31, w = t >> 5;
    int rg = w / CG, cg = w % CG;         // rg = point index within tile
    int p0 = blockIdx.x * 8;
    int b  = p0 / Nn;
    if (t < ED) sidx[t] = d_knn[p0 * KNN + t];
    for (int idx = t; idx < 8 * CIN; idx += NT)
        sxi[idx] = x[(size_t)(p0 + idx / CIN) * ld + off + (idx % CIN)];
    __syncthreads();
    // E^T[2CIN][ED]: row r = point (r>>3), neighbor (r&7)
    for (int idx = t; idx < ED * (CIN / 4); idx += NT) {
        int r = idx & (ED - 1), c4 = idx / ED;
        float4 v = *(const float4*)(x + ((size_t)b * Nn + sidx[r]) * ld + off + c4 * 4);
        const float* xi = sxi + (r >> 3) * CIN + c4 * 4;
        float i0 = xi[0], i1 = xi[1], i2 = xi[2], i3 = xi[3];
        Et[(c4 * 4 + 0) * MP + r] = i0;
        Et[(c4 * 4 + 1) * MP + r] = i1;
        Et[(c4 * 4 + 2) * MP + r] = i2;
        Et[(c4 * 4 + 3) * MP + r] = i3;
        Et[(CIN + c4 * 4 + 0) * MP + r] = v.x - i0;
        Et[(CIN + c4 * 4 + 1) * MP + r] = v.y - i1;
        Et[(CIN + c4 * 4 + 2) * MP + r] = v.z - i2;
        Et[(CIN + c4 * 4 + 3) * MP + r] = v.w - i3;
    }
    __syncthreads();
    // GEMM1: Ht = relu(E*W1 + b1)
    unsigned long long acc[8][2];
    #pragma unroll
    for (int m = 0; m < 8; m++) { acc[m][0] = 0ull; acc[m][1] = 0ull; }
    gemm_t8<K1, NC1, MP, NT, CG, PP1>(Et, w1, H, 0, Wt, acc, tx, rg, cg, t);
    #pragma unroll
    for (int p = 0; p < PP1; p++) {
        int u0 = cg * (NC1 / CG) + (tx + p * 32) * 2;
        float bb0 = b1[u0], bb1 = b1[u0 + 1];
        #pragma unroll
        for (int m = 0; m < 8; m++) {
            float lo, hi; unpk(acc[m][p], lo, hi);
            Ht[u0 * MP + rg * 8 + m]       = fmaxf(lo + bb0, 0.f);
            Ht[(u0 + 1) * MP + rg * 8 + m] = fmaxf(hi + bb1, 0.f);
        }
    }
    __syncthreads();
    // GEMM2 + in-register max over the 8 neighbors (thread's 8 rows = point rg)
    for (int col0 = 0; col0 < COUT; col0 += NC2) {
        #pragma unroll
        for (int m = 0; m < 8; m++) { acc[m][0] = 0ull; acc[m][1] = 0ull; }
        gemm_t8<H, NC2, MP, NT, CG, PP2>(Ht, w2, COUT, col0, Wt, acc, tx, rg, cg, t);
        #pragma unroll
        for (int p = 0; p < PP2; p++) {
            int u0 = col0 + cg * (NC2 / CG) + (tx + p * 32) * 2;
            float m0 = -3.4e38f, m1 = -3.4e38f;
            #pragma unroll
            for (int m = 0; m < 8; m++) {
                float lo, hi; unpk(acc[m][p], lo, hi);
                m0 = fmaxf(m0, lo);
                m1 = fmaxf(m1, hi);
            }
            float* o = d_feat + (size_t)(p0 + rg) * FEAT + off_out + u0;
            o[0] = m0 + b2[u0];
            o[1] = m1 + b2[u0 + 1];
        }
    }
}

// ---------------- EdgeConv stage 1 (3->6->16->32), parallel over (k,u)/(k,o) --
__global__ __launch_bounds__(256) void edgeconv1(
    const float* __restrict__ x,
    const float* __restrict__ w1, const float* __restrict__ b1,
    const float* __restrict__ w2, const float* __restrict__ b2)
{
    __shared__ float se[KNN][8];
    __shared__ float sh[KNN][16];
    __shared__ float sp[KNN][32];
    __shared__ float sxi[3];
    __shared__ int   sidx[KNN];
    int row = blockIdx.x;
    int b   = row / Nn;
    int t   = threadIdx.x;
    if (t < 3) sxi[t] = x[(size_t)row * 3 + t];
    if (t < KNN) sidx[t] = d_knn[row * KNN + t];
    __syncthreads();
    if (t < 24) {
        int k = t / 3, c = t % 3;
        float xj = x[((size_t)b * Nn + sidx[k]) * 3 + c];
        se[k][c]     = sxi[c];
        se[k][3 + c] = xj - sxi[c];
    }
    __syncthreads();
    if (t < 128) {
        int u = t & 15, k = t >> 4;
        float a = b1[u];
        #pragma unroll
        for (int c = 0; c < 6; c++) a += se[k][c] * w1[c * 16 + u];
        sh[k][u] = a > 0.f ? a : 0.f;
    }
    __syncthreads();
    {
        int o = t & 31, k = t >> 5;
        float a = 0.f;
        #pragma unroll
        for (int u = 0; u < 16; u++) a += sh[k][u] * w2[u * 32 + o];
        sp[k][o] = a;
    }
    __syncthreads();
    if (t < 32) {
        float m = sp[0][t];
        #pragma unroll
        for (int k = 1; k < KNN; k++) m = fmaxf(m, sp[k][t]);
        d_feat[(size_t)row * FEAT + t] = m + b2[t];
    }
}

// ---------------- sf-MLP batched: 16 points per CTA ----------------
template <int KK, int NC, int TM, int MP>
__device__ __forceinline__ void gemm_f2(
    const float* __restrict__ At, const float* __restrict__ Wg, int ldw, int col0,
    float* __restrict__ Wt, unsigned long long (&acc)[TM][4], int tx, int ty, int t)
{
    constexpr int P2 = NC / 64;
    for (int kb = 0; kb < KK; kb += 32) {
        for (int idx = t; idx < 32 * (NC / 4); idx += 256) {
            int c  = idx / (NC / 4);
            int u4 = idx - c * (NC / 4);
            ((float4*)Wt)[idx] = *(const float4*)(Wg + (size_t)(kb + c) * ldw + col0 + u4 * 4);
        }
        __syncthreads();
        #pragma unroll 4
        for (int c = 0; c < 32; c++) {
            const float* arow = At + (kb + c) * MP + ty * TM;
            float2 a = *(const float2*)(arow);
            unsigned long long ep0 = pack2(a.x), ep1 = pack2(a.y);
            const unsigned long long* wrow = (const unsigned long long*)(Wt + c * NC);
            #pragma unroll
            for (int p = 0; p < P2; p++) {
                unsigned long long wv = wrow[tx + p * 32];
                FFMA2(acc[0][p], ep0, wv);
                FFMA2(acc[1 % TM][p], ep1, wv);
            }
        }
        __syncthreads();
    }
}

__global__ __launch_bounds__(256) void sfmlp_b(
    const float* __restrict__ w1, const float* __restrict__ b1,
    const float* __restrict__ w2, const float* __restrict__ b2)
{
    constexpr int MP = 20;
    extern __shared__ float sm[];
    float* Xt = sm;
    float* Ht = Xt + FEAT * MP;
    float* Wt = Ht + 256 * MP;
    int t = threadIdx.x, tx = t & 31, ty = t >> 5;
    int p0 = blockIdx.x * 16;
    for (int idx = t; idx < 16 * (FEAT / 4); idx += 256) {
        int r = idx & 15, c4 = idx >> 4;
        float4 v = *(const float4*)(d_feat + (size_t)(p0 + r) * FEAT + c4 * 4);
        Xt[(c4 * 4 + 0) * MP + r] = v.x;
        Xt[(c4 * 4 + 1) * MP + r] = v.y;
        Xt[(c4 * 4 + 2) * MP + r] = v.z;
        Xt[(c4 * 4 + 3) * MP + r] = v.w;
    }
    __syncthreads();
    unsigned long long acc[2][4];
    #pragma unroll
    for (int m = 0; m < 2; m++)
        #pragma unroll
        for (int p = 0; p < 4; p++) acc[m][p] = 0ull;
    gemm_f2<FEAT, 256, 2, MP>(Xt, w1, 256, 0, Wt, acc, tx, ty, t);
    #pragma unroll
    for (int p = 0; p < 4; p++) {
        int u0 = tx * 2 + p * 64;
        float bb0 = b1[u0], bb1 = b1[u0 + 1];
        #pragma unroll
        for (int m = 0; m < 2; m++) {
            float lo, hi; unpk(acc[m][p], lo, hi);
            Ht[u0 * MP + ty * 2 + m]       = fmaxf(lo + bb0, 0.f);
            Ht[(u0 + 1) * MP + ty * 2 + m] = fmaxf(hi + bb1, 0.f);
        }
    }
    __syncthreads();
    #pragma unroll
    for (int m = 0; m < 2; m++)
        #pragma unroll
        for (int p = 0; p < 4; p++) acc[m][p] = 0ull;
    gemm_f2<256, 128, 2, MP>(Ht, w2, 128, 0, Wt, acc, tx, ty, t);
    #pragma unroll
    for (int p = 0; p < 2; p++) {
        int u0 = tx * 2 + p * 64;
        float bb0 = b2[u0], bb1 = b2[u0 + 1];
        #pragma unroll
        for (int m = 0; m < 2; m++) {
            float lo, hi; unpk(acc[m][p], lo, hi);
            float* o = d_sf + (size_t)(p0 + ty * 2 + m) * 128 + u0;
            o[0] = lo + bb0; o[1] = hi + bb1;
        }
    }
}

// ---------------- global max pool: partial + final ----------------
__global__ void gmax_part() {
    int b = blockIdx.x, s = blockIdx.y, o = threadIdx.x;
    const float* p = d_sf + ((size_t)b * Nn + s * 125) * 128 + o;
    float m0 = -3.4e38f, m1 = -3.4e38f, m2 = -3.4e38f, m3 = -3.4e38f;
    for (int n = 0; n < 124; n += 4) {
        m0 = fmaxf(m0, p[(n + 0) * 128]);
        m1 = fmaxf(m1, p[(n + 1) * 128]);
        m2 = fmaxf(m2, p[(n + 2) * 128]);
        m3 = fmaxf(m3, p[(n + 3) * 128]);
    }
    m0 = fmaxf(m0, p[124 * 128]);
    d_gp[(b * 8 + s) * 128 + o] = fmaxf(fmaxf(m0, m1), fmaxf(m2, m3));
}
__global__ void gmax_fin() {
    int t = threadIdx.x;
    int b = t >> 7, o = t & 127;
    float m = -3.4e38f;
    #pragma unroll
    for (int s = 0; s < 8; s++) m = fmaxf(m, d_gp[(b * 8 + s) * 128 + o]);
    d_g[b * 128 + o] = m;
}

// ---------------- hi/hj projection: 8 points per CTA ----------------
__global__ __launch_bounds__(256) void hij_b(const float* __restrict__ ecw1) {
    __shared__ float st[128][10];
    int t = threadIdx.x;
    int p0 = blockIdx.x * 8;
    for (int idx = t; idx < 8 * 128; idx += 256) {
        int r = idx >> 7, d = idx & 127;
        st[d][r] = d_sf[(size_t)(p0 + r) * 128 + d];
    }
    __syncthreads();
    int col = t & 127, which = t >> 7;
    const float* w = ecw1 + (size_t)which * 128 * 128 + col;
    unsigned long long acc[4] = {0ull, 0ull, 0ull, 0ull};
    for (int d = 0; d < 128; d++) {
        unsigned long long wv = pack2(w[(size_t)d * 128]);
        const unsigned long long* sp = (const unsigned long long*)(&st[d][0]);
        #pragma unroll
        for (int m = 0; m < 4; m++) FFMA2(acc[m], sp[m], wv);
    }
    float* out = which ? d_hj : d_hi;
    #pragma unroll
    for (int m = 0; m < 4; m++) {
        float lo, hi; unpk(acc[m], lo, hi);
        out[(size_t)(p0 + 2 * m) * 128 + col]     = lo;
        out[(size_t)(p0 + 2 * m + 1) * 128 + col] = hi;
    }
}

// ---------------- hg = g @ W[256:] + b1 ----------------
__global__ void hg_kernel(const float* __restrict__ ecw1, const float* __restrict__ ecb1) {
    int t = threadIdx.x;
    int b = t >> 7, o = t & 127;
    float acc = ecb1[o];
    for (int d = 0; d < 128; d++) acc += d_g[b * 128 + d] * ecw1[(256 + d) * 128 + o];
    d_hg[b * 128 + o] = acc;
}

// ---------------- pair scorer: 32x32 tiles, 2x2 register tiling ----------------
#define TILE 32
#define PADC 132
__global__ __launch_bounds__(256) void pair_kernel(
    const float* __restrict__ ecw2, const float* __restrict__ ecb2,
    float* __restrict__ out, int write_logits)
{
    __shared__ __align__(16) float shi[TILE][PADC];
    __shared__ __align__(16) float shj[TILE][PADC];
    __shared__ __align__(16) float shg[128];
    __shared__ __align__(16) float sw2[128];
    int jt = blockIdx.x, it = blockIdx.y, b = blockIdx.z;
    if (jt < it) return;
    int t  = threadIdx.x;
    int i0 = it * TILE, j0 = jt * TILE;
    if (t < 128) { shg[t] = d_hg[b * 128 + t]; sw2[t] = ecw2[t]; }
    __syncthreads();
    for (int idx = t; idx < TILE * 128; idx += 256) {
        int r = idx >> 7, u = idx & 127;
        int gi = i0 + r, gj = j0 + r;
        shi[r][u] = (gi < Nn) ? d_hi[((size_t)b * Nn + gi) * 128 + u] + shg[u] : 0.f;
        shj[r][u] = (gj < Nn) ? d_hj[((size_t)b * Nn + gj) * 128 + u] : 0.f;
    }
    __syncthreads();
    float bias = ecb2[0];
    const long P = (long)Nn * (Nn - 1) / 2;
    int ii = t >> 4;
    int jj = t & 15;
    float a00 = 0.f, a01 = 0.f, a10 = 0.f, a11 = 0.f;
    const float4* vi0 = (const float4*)shi[ii];
    const float4* vi1 = (const float4*)shi[ii + 16];
    const float4* vj0 = (const float4*)shj[jj];
    const float4* vj1 = (const float4*)shj[jj + 16];
    const float4* vw  = (const float4*)sw2;
    #pragma unroll
    for (int q = 0; q < 32; q++) {
        float4 A0 = vi0[q], A1 = vi1[q], B0 = vj0[q], B1 = vj1[q], w = vw[q];
        a00 += fmaxf(A0.x + B0.x, 0.f) * w.x; a00 += fmaxf(A0.y + B0.y, 0.f) * w.y;
        a00 += fmaxf(A0.z + B0.z, 0.f) * w.z; a00 += fmaxf(A0.w + B0.w, 0.f) * w.w;
        a01 += fmaxf(A0.x + B1.x, 0.f) * w.x; a01 += fmaxf(A0.y + B1.y, 0.f) * w.y;
        a01 += fmaxf(A0.z + B1.z, 0.f) * w.z; a01 += fmaxf(A0.w + B1.w, 0.f) * w.w;
        a10 += fmaxf(A1.x + B0.x, 0.f) * w.x; a10 += fmaxf(A1.y + B0.y, 0.f) * w.y;
        a10 += fmaxf(A1.z + B0.z, 0.f) * w.z; a10 += fmaxf(A1.w + B0.w, 0.f) * w.w;
        a11 += fmaxf(A1.x + B1.x, 0.f) * w.x; a11 += fmaxf(A1.y + B1.y, 0.f) * w.y;
        a11 += fmaxf(A1.z + B1.z, 0.f) * w.z; a11 += fmaxf(A1.w + B1.w, 0.f) * w.w;
    }
    float accs[2][2] = {{a00, a01}, {a10, a11}};
    #pragma unroll
    for (int a = 0; a < 2; a++) {
        #pragma unroll
        for (int c = 0; c < 2; c++) {
            int i = i0 + ii + a * 16;
            int j = j0 + jj + c * 16;
            if (i < Nn && j < Nn && i < j) {
                float logit = accs[a][c] + bias;
                long pidx = (long)b * P + (long)i * (2 * Nn - i - 1) / 2 + (j - i - 1);
                out[pidx] = 1.f / (1.f + __expf(-logit));
                if (write_logits) out[(long)Bb * P + pidx] = logit;
            }
        }
    }
}

extern "C" void kernel_launch(void* const* d_in, const int* in_sizes, int n_in,
                              void* d_out, int out_size) {
    const float* pos  = (const float*)d_in[0];
    const float* c1w1 = (const float*)d_in[1];
    const float* c1b1 = (const float*)d_in[2];
    const float* c1w2 = (const float*)d_in[3];
    const float* c1b2 = (const float*)d_in[4];
    const float* c2w1 = (const float*)d_in[5];
    const float* c2b1 = (const float*)d_in[6];
    const float* c2w2 = (const float*)d_in[7];
    const float* c2b2 = (const float*)d_in[8];
    const float* c3w1 = (const float*)d_in[9];
    const float* c3b1 = (const float*)d_in[10];
    const float* c3w2 = (const float*)d_in[11];
    const float* c3b2 = (const float*)d_in[12];
    const float* smw1 = (const float*)d_in[13];
    const float* smb1 = (const float*)d_in[14];
    const float* smw2 = (const float*)d_in[15];
    const float* smb2 = (const float*)d_in[16];
    const float* ecw1 = (const float*)d_in[17];
    const float* ecb1 = (const float*)d_in[18];
    const float* ecw2 = (const float*)d_in[19];
    const float* ecb2 = (const float*)d_in[20];
    float* out = (float*)d_out;

    const long P = (long)Nn * (Nn - 1) / 2;
    int write_logits = ((long)out_size >= 2L * Bb * P) ? 1 : 0;

    float* feat = nullptr;
    cudaGetSymbolAddress((void**)&feat, d_feat);

    // dynamic smem: sxi + Et + Ht + Wt (floats)
    const int SM2 = (8 * 32 + 64 * 68 + 64 * 68 + 32 * 128) * 4;       // 52,224 B
    const int SM3 = (8 * 128 + 256 * 68 + 256 * 68 + 32 * 256) * 4;    // 176,128 B
    const int SMS = (FEAT * 20 + 256 * 20 + 32 * 256) * 4;             // 107,008 B
    cudaFuncSetAttribute(edgeconv8<32, 64, 128, 256, 1>,   cudaFuncAttributeMaxDynamicSharedMemorySize, SM2);
    cudaFuncSetAttribute(edgeconv8<128, 256, 512, 512, 2>, cudaFuncAttributeMaxDynamicSharedMemorySize, SM3);
    cudaFuncSetAttribute(sfmlp_b, cudaFuncAttributeMaxDynamicSharedMemorySize, SMS);

    // stage 1: kNN on pos (C=3), EdgeConv 6->16->32 -> feat[:,0:32]
    knn_b<3><<<250, 256>>>(pos, 3, 0);
    edgeconv1<<<Bb * Nn, 256>>>(pos, c1w1, c1b1, c1w2, c1b2);

    // stage 2: kNN on x1 (C=32), EdgeConv 64->64->128 -> feat[:,32:160]
    knn_b<32><<<250, 256>>>(feat, FEAT, 0);
    edgeconv8<32, 64, 128, 256, 1><<<250, 256, SM2>>>(feat, FEAT, 0, 32, c2w1, c2b1, c2w2, c2b2);

    // stage 3: kNN on x2 (C=128), EdgeConv 256->256->512 -> feat[:,160:672]
    knn_b<128><<<250, 256>>>(feat, FEAT, 32);
    edgeconv8<128, 256, 512, 512, 2><<<250, 512, SM3>>>(feat, FEAT, 32, 160, c3w1, c3b1, c3w2, c3b2);

    // sf MLP, global max, pair projections
    sfmlp_b<<<125, 256, SMS>>>(smw1, smb1, smw2, smb2);
    dim3 gg(Bb, 8);
    gmax_part<<<gg, 128>>>();
    gmax_fin<<<1, 256>>>();
    hij_b<<<250, 256>>>(ecw1);
    hg_kernel<<<1, 256>>>(ecw1, ecb1);

    // pair scorer
    dim3 pg((Nn + TILE - 1) / TILE, (Nn + TILE - 1) / TILE, Bb);
    pair_kernel<<<pg, 256>>>(ecw2, ecb2, out, write_logits);
}

// round 14
// speedup vs baseline: 1.1228x; 1.0974x over previous
#include <cuda_runtime.h>
#include <math.h>

#define Bb 2
#define Nn 1000
#define KNN 8
#define FEAT 672
#define DPAIR 128

// ---------------- scratch (device globals; no allocation) ----------------
__device__ int   d_knn[Bb * Nn * KNN];
__device__ float d_feat[Bb * Nn * FEAT];    // x1 | x2 | x3 packed at cols 0,32,160
__device__ float d_sf[Bb * Nn * DPAIR];
__device__ float d_gp[Bb * 8 * DPAIR];
__device__ float d_g[Bb * DPAIR];
__device__ float d_hi[Bb * Nn * DPAIR];
__device__ float d_hj[Bb * Nn * DPAIR];
__device__ float d_hg[Bb * DPAIR];
__device__ float d_vu[Bb * Nn * 512];       // per-point [w | u] rows (ld = 2H)
__device__ float d_wc[256 * 512];           // combined weight [CIN][2H]

// ---------------- f32x2 packed helpers ----------------
__device__ __forceinline__ unsigned long long pack2(float v) {
    unsigned long long r;
    asm("mov.b64 %0, {%1, %1};" : "=l"(r) : "f"(v));
    return r;
}
__device__ __forceinline__ unsigned long long packab(float a, float b) {
    unsigned long long r;
    asm("mov.b64 %0, {%1, %2};" : "=l"(r) : "f"(a), "f"(b));
    return r;
}
#define FFMA2(acc, a, b) asm("fma.rn.f32x2 %0, %1, %2, %0;" : "+l"(acc) : "l"(a), "l"(b))
__device__ __forceinline__ void unpk(unsigned long long v, float& lo, float& hi) {
    asm("mov.b64 {%0, %1}, %2;" : "=f"(lo), "=f"(hi) : "l"(v));
}
__device__ __forceinline__ float hsum2(unsigned long long v) {
    float lo, hi; unpk(v, lo, hi); return lo + hi;
}

// ---------------- kNN batched: 8 points per CTA ----------------
template <int C>
__global__ __launch_bounds__(256) void knn_b(const float* __restrict__ x, int ld, int off) {
    __shared__ float sd2[8][Nn];
    __shared__ float sxi[8][C];
    int t  = threadIdx.x;
    int p0 = blockIdx.x * 8;
    int b  = p0 / Nn;
    for (int idx = t; idx < 8 * C; idx += 256)
        sxi[idx / C][idx % C] = x[(size_t)(p0 + idx / C) * ld + off + (idx % C)];
    __syncthreads();
    const float* xb = x + (size_t)b * Nn * ld + off;
    for (int j = t; j < Nn; j += 256) {
        if (C % 4 == 0) {
            const float4* xp = (const float4*)(xb + (size_t)j * ld);
            unsigned long long acc[8], nrm = 0ull;
            #pragma unroll
            for (int r = 0; r < 8; r++) acc[r] = 0ull;
            #pragma unroll
            for (int c4 = 0; c4 < C / 4; c4++) {
                float4 v = xp[c4];
                unsigned long long v01 = packab(v.x, v.y);
                unsigned long long v23 = packab(v.z, v.w);
                FFMA2(nrm, v01, v01);
                FFMA2(nrm, v23, v23);
                #pragma unroll
                for (int r = 0; r < 8; r++) {
                    const unsigned long long* s = (const unsigned long long*)(sxi[r]);
                    FFMA2(acc[r], v01, s[2 * c4]);
                    FFMA2(acc[r], v23, s[2 * c4 + 1]);
                }
            }
            float sqj = hsum2(nrm);
            #pragma unroll
            for (int r = 0; r < 8; r++)
                sd2[r][j] = fmaf(-2.f, hsum2(acc[r]), sqj);   // sq_i constant per row: dropped
        } else {
            const float* xj = xb + (size_t)j * ld;
            float v0 = xj[0], v1 = xj[1], v2 = xj[2];
            float sqj = v0 * v0 + v1 * v1 + v2 * v2;
            #pragma unroll
            for (int r = 0; r < 8; r++) {
                float dot = sxi[r][0] * v0 + sxi[r][1] * v1 + sxi[r][2] * v2;
                sd2[r][j] = fmaf(-2.f, dot, sqj);
            }
        }
    }
    __syncthreads();
    int w = t >> 5, lane = t & 31;
    float* row = sd2[w];
    for (int k = 0; k < KNN; k++) {
        float bv = 3.4e38f; int bi = Nn;
        for (int j = lane; j < Nn; j += 32) {
            float v = row[j];
            if (v < bv) { bv = v; bi = j; }
        }
        #pragma unroll
        for (int o = 16; o > 0; o >>= 1) {
            float ov = __shfl_down_sync(0xffffffffu, bv, o);
            int   oi = __shfl_down_sync(0xffffffffu, bi, o);
            if (ov < bv || (ov == bv && oi < bi)) { bv = ov; bi = oi; }
        }
        bi = __shfl_sync(0xffffffffu, bi, 0);
        if (lane == 0) { d_knn[(p0 + w) * KNN + k] = bi; row[bi] = 3.4e38f; }
        __syncwarp();
    }
}

// ---------------- wcomb: d_wc[c][0:H] = W1t-W1b, [c][H:2H] = W1b ----------------
__global__ void wcomb_kernel(const float* __restrict__ w1, int CIN, int H) {
    int idx = blockIdx.x * 256 + threadIdx.x;
    if (idx >= CIN * H) return;
    int c = idx / H, u = idx % H;
    float top = w1[c * H + u];
    float bot = w1[(CIN + c) * H + u];
    d_wc[c * 2 * H + u]     = top - bot;
    d_wc[c * 2 * H + H + u] = bot;
}

// ---------------- generic f32x2 GEMM tile (TM=2), 256 threads ----------------
template <int KK, int NC, int TM, int MP>
__device__ __forceinline__ void gemm_f2(
    const float* __restrict__ At, const float* __restrict__ Wg, int ldw, int col0,
    float* __restrict__ Wt, unsigned long long (&acc)[TM][4], int tx, int ty, int t)
{
    constexpr int P2 = NC / 64;
    for (int kb = 0; kb < KK; kb += 32) {
        for (int idx = t; idx < 32 * (NC / 4); idx += 256) {
            int c  = idx / (NC / 4);
            int u4 = idx - c * (NC / 4);
            ((float4*)Wt)[idx] = *(const float4*)(Wg + (size_t)(kb + c) * ldw + col0 + u4 * 4);
        }
        __syncthreads();
        #pragma unroll 4
        for (int c = 0; c < 32; c++) {
            const float* arow = At + (kb + c) * MP + ty * TM;
            float2 a = *(const float2*)(arow);
            unsigned long long ep0 = pack2(a.x), ep1 = pack2(a.y);
            const unsigned long long* wrow = (const unsigned long long*)(Wt + c * NC);
            #pragma unroll
            for (int p = 0; p < P2; p++) {
                unsigned long long wv = wrow[tx + p * 32];
                FFMA2(acc[0][p], ep0, wv);
                FFMA2(acc[1 % TM][p], ep1, wv);
            }
        }
        __syncthreads();
    }
}

// ---------------- pregemm: VU[2000][2H] = x @ d_wc, 16 points per CTA --------
template <int CIN, int HH>
__global__ __launch_bounds__(256) void pregemm(
    const float* __restrict__ x, int ld, int off)
{
    constexpr int MP  = 20;
    constexpr int NC2 = (2 * HH > 256) ? 256 : 2 * HH;
    extern __shared__ float sm[];
    float* Xt = sm;                 // CIN*20
    float* Wt = Xt + CIN * MP;      // 32*NC2
    int t = threadIdx.x, tx = t & 31, ty = t >> 5;
    int p0 = blockIdx.x * 16;
    for (int idx = t; idx < 16 * (CIN / 4); idx += 256) {
        int r = idx & 15, c4 = idx >> 4;
        float4 v = *(const float4*)(x + (size_t)(p0 + r) * ld + off + c4 * 4);
        Xt[(c4 * 4 + 0) * MP + r] = v.x;
        Xt[(c4 * 4 + 1) * MP + r] = v.y;
        Xt[(c4 * 4 + 2) * MP + r] = v.z;
        Xt[(c4 * 4 + 3) * MP + r] = v.w;
    }
    __syncthreads();
    for (int col0 = 0; col0 < 2 * HH; col0 += NC2) {
        unsigned long long acc[2][4];
        #pragma unroll
        for (int m = 0; m < 2; m++)
            #pragma unroll
            for (int p = 0; p < 4; p++) acc[m][p] = 0ull;
        gemm_f2<CIN, NC2, 2, MP>(Xt, d_wc, 2 * HH, col0, Wt, acc, tx, ty, t);
        constexpr int P2 = NC2 / 64;
        #pragma unroll
        for (int p = 0; p < P2; p++) {
            int u0 = tx * 2 + p * 64;
            #pragma unroll
            for (int m = 0; m < 2; m++) {
                float lo, hi; unpk(acc[m][p], lo, hi);
                float* o = d_vu + (size_t)(p0 + ty * 2 + m) * (2 * HH) + col0 + u0;
                o[0] = lo; o[1] = hi;
            }
        }
    }
}

// ---------------- f32x2 GEMM, TM=8 rows/thread (rows = one point's edges) ----
template <int KK, int NC, int MP, int NT, int CG, int PP>
__device__ __forceinline__ void gemm_t8(
    const float* __restrict__ At, const float* __restrict__ Wg, int ldw, int col0,
    float* __restrict__ Wt, unsigned long long (&acc)[8][2], int tx, int rg, int cg, int t)
{
    for (int kb = 0; kb < KK; kb += 32) {
        for (int idx = t; idx < 32 * (NC / 4); idx += NT) {
            int c  = idx / (NC / 4);
            int u4 = idx - c * (NC / 4);
            ((float4*)Wt)[idx] = *(const float4*)(Wg + (size_t)(kb + c) * ldw + col0 + u4 * 4);
        }
        __syncthreads();
        #pragma unroll 4
        for (int c = 0; c < 32; c++) {
            const float* ar = At + (kb + c) * MP + rg * 8;
            float4 a0 = *(const float4*)ar;            // broadcast within warp
            float4 a1 = *(const float4*)(ar + 4);
            unsigned long long e0 = pack2(a0.x), e1 = pack2(a0.y);
            unsigned long long e2 = pack2(a0.z), e3 = pack2(a0.w);
            unsigned long long e4 = pack2(a1.x), e5 = pack2(a1.y);
            unsigned long long e6 = pack2(a1.z), e7 = pack2(a1.w);
            const unsigned long long* wr =
                (const unsigned long long*)(Wt + c * NC) + cg * (NC / CG / 2);
            #pragma unroll
            for (int p = 0; p < PP; p++) {
                unsigned long long wv = wr[tx + p * 32];
                FFMA2(acc[0][p], e0, wv);
                FFMA2(acc[1][p], e1, wv);
                FFMA2(acc[2][p], e2, wv);
                FFMA2(acc[3][p], e3, wv);
                FFMA2(acc[4][p], e4, wv);
                FFMA2(acc[5][p], e5, wv);
                FFMA2(acc[6][p], e6, wv);
                FFMA2(acc[7][p], e7, wv);
            }
        }
        __syncthreads();
    }
}

// ---------------- ecpre: Ht = relu(w_i + u_j + b1) gather, GEMM2 + max -------
// 4 points (32 edges) per CTA. NT = 128*CG. warp w: rg = w/CG (point), cg = w%CG.
template <int H, int COUT, int CG>
__global__ __launch_bounds__(128 * CG) void ecpre(
    int off_out,
    const float* __restrict__ b1,
    const float* __restrict__ w2, const float* __restrict__ b2)
{
    constexpr int NT  = 128 * CG;
    constexpr int ED  = 32;
    constexpr int MP  = 36;
    constexpr int NC2 = (COUT > 256) ? 256 : COUT;
    constexpr int PP2 = NC2 / CG / 64;
    extern __shared__ float sm[];
    float* sw = sm;                 // 4*H   (w_i rows)
    float* Ht = sw + 4 * H;         // H*MP
    float* Wt = Ht + H * MP;        // 32*NC2
    __shared__ int sidx[ED];
    int t = threadIdx.x, tx = t & 31, w = t >> 5;
    int rg = w / CG, cg = w % CG;
    int p0 = blockIdx.x * 4;
    int b  = p0 / Nn;
    if (t < ED) sidx[t] = d_knn[p0 * KNN + t];
    for (int idx = t; idx < H; idx += NT) {         // 4 rows of w_i
        #pragma unroll
        for (int p = 0; p < 4; p++)
            sw[p * H + idx] = d_vu[(size_t)(p0 + p) * (2 * H) + idx];
    }
    __syncthreads();
    // build Ht[u][r] = relu(w_i[u] + u_j[u] + b1[u])
    for (int idx = t; idx < ED * (H / 4); idx += NT) {
        int r = idx & 31, c4 = idx >> 5;
        int j = sidx[r];
        float4 uj = *(const float4*)(d_vu + ((size_t)b * Nn + j) * (2 * H) + H + c4 * 4);
        const float* wr = sw + (r >> 3) * H + c4 * 4;
        float4 bv = *(const float4*)(b1 + c4 * 4);
        Ht[(c4 * 4 + 0) * MP + r] = fmaxf(wr[0] + uj.x + bv.x, 0.f);
        Ht[(c4 * 4 + 1) * MP + r] = fmaxf(wr[1] + uj.y + bv.y, 0.f);
        Ht[(c4 * 4 + 2) * MP + r] = fmaxf(wr[2] + uj.z + bv.z, 0.f);
        Ht[(c4 * 4 + 3) * MP + r] = fmaxf(wr[3] + uj.w + bv.w, 0.f);
    }
    __syncthreads();
    // GEMM2 + in-register max over the 8 neighbors (thread's 8 rows = point rg)
    for (int col0 = 0; col0 < COUT; col0 += NC2) {
        unsigned long long acc[8][2];
        #pragma unroll
        for (int m = 0; m < 8; m++) { acc[m][0] = 0ull; acc[m][1] = 0ull; }
        gemm_t8<H, NC2, MP, NT, CG, PP2>(Ht, w2, COUT, col0, Wt, acc, tx, rg, cg, t);
        #pragma unroll
        for (int p = 0; p < PP2; p++) {
            int u0 = col0 + cg * (NC2 / CG) + (tx + p * 32) * 2;
            float m0 = -3.4e38f, m1 = -3.4e38f;
            #pragma unroll
            for (int m = 0; m < 8; m++) {
                float lo, hi; unpk(acc[m][p], lo, hi);
                m0 = fmaxf(m0, lo);
                m1 = fmaxf(m1, hi);
            }
            float* o = d_feat + (size_t)(p0 + rg) * FEAT + off_out + u0;
            o[0] = m0 + b2[u0];
            o[1] = m1 + b2[u0 + 1];
        }
    }
}

// ---------------- EdgeConv stage 1 (3->6->16->32) ----------------
__global__ __launch_bounds__(256) void edgeconv1(
    const float* __restrict__ x,
    const float* __restrict__ w1, const float* __restrict__ b1,
    const float* __restrict__ w2, const float* __restrict__ b2)
{
    __shared__ float se[KNN][8];
    __shared__ float sh[KNN][16];
    __shared__ float sp[KNN][32];
    __shared__ float sxi[3];
    __shared__ int   sidx[KNN];
    int row = blockIdx.x;
    int b   = row / Nn;
    int t   = threadIdx.x;
    if (t < 3) sxi[t] = x[(size_t)row * 3 + t];
    if (t < KNN) sidx[t] = d_knn[row * KNN + t];
    __syncthreads();
    if (t < 24) {
        int k = t / 3, c = t % 3;
        float xj = x[((size_t)b * Nn + sidx[k]) * 3 + c];
        se[k][c]     = sxi[c];
        se[k][3 + c] = xj - sxi[c];
    }
    __syncthreads();
    if (t < 128) {
        int u = t & 15, k = t >> 4;
        float a = b1[u];
        #pragma unroll
        for (int c = 0; c < 6; c++) a += se[k][c] * w1[c * 16 + u];
        sh[k][u] = a > 0.f ? a : 0.f;
    }
    __syncthreads();
    {
        int o = t & 31, k = t >> 5;
        float a = 0.f;
        #pragma unroll
        for (int u = 0; u < 16; u++) a += sh[k][u] * w2[u * 32 + o];
        sp[k][o] = a;
    }
    __syncthreads();
    if (t < 32) {
        float m = sp[0][t];
        #pragma unroll
        for (int k = 1; k < KNN; k++) m = fmaxf(m, sp[k][t]);
        d_feat[(size_t)row * FEAT + t] = m + b2[t];
    }
}

// ---------------- sf-MLP batched: 16 points per CTA ----------------
__global__ __launch_bounds__(256) void sfmlp_b(
    const float* __restrict__ w1, const float* __restrict__ b1,
    const float* __restrict__ w2, const float* __restrict__ b2)
{
    constexpr int MP = 20;
    extern __shared__ float sm[];
    float* Xt = sm;
    float* Ht = Xt + FEAT * MP;
    float* Wt = Ht + 256 * MP;
    int t = threadIdx.x, tx = t & 31, ty = t >> 5;
    int p0 = blockIdx.x * 16;
    for (int idx = t; idx < 16 * (FEAT / 4); idx += 256) {
        int r = idx & 15, c4 = idx >> 4;
        float4 v = *(const float4*)(d_feat + (size_t)(p0 + r) * FEAT + c4 * 4);
        Xt[(c4 * 4 + 0) * MP + r] = v.x;
        Xt[(c4 * 4 + 1) * MP + r] = v.y;
        Xt[(c4 * 4 + 2) * MP + r] = v.z;
        Xt[(c4 * 4 + 3) * MP + r] = v.w;
    }
    __syncthreads();
    unsigned long long acc[2][4];
    #pragma unroll
    for (int m = 0; m < 2; m++)
        #pragma unroll
        for (int p = 0; p < 4; p++) acc[m][p] = 0ull;
    gemm_f2<FEAT, 256, 2, MP>(Xt, w1, 256, 0, Wt, acc, tx, ty, t);
    #pragma unroll
    for (int p = 0; p < 4; p++) {
        int u0 = tx * 2 + p * 64;
        float bb0 = b1[u0], bb1 = b1[u0 + 1];
        #pragma unroll
        for (int m = 0; m < 2; m++) {
            float lo, hi; unpk(acc[m][p], lo, hi);
            Ht[u0 * MP + ty * 2 + m]       = fmaxf(lo + bb0, 0.f);
            Ht[(u0 + 1) * MP + ty * 2 + m] = fmaxf(hi + bb1, 0.f);
        }
    }
    __syncthreads();
    #pragma unroll
    for (int m = 0; m < 2; m++)
        #pragma unroll
        for (int p = 0; p < 4; p++) acc[m][p] = 0ull;
    gemm_f2<256, 128, 2, MP>(Ht, w2, 128, 0, Wt, acc, tx, ty, t);
    #pragma unroll
    for (int p = 0; p < 2; p++) {
        int u0 = tx * 2 + p * 64;
        float bb0 = b2[u0], bb1 = b2[u0 + 1];
        #pragma unroll
        for (int m = 0; m < 2; m++) {
            float lo, hi; unpk(acc[m][p], lo, hi);
            float* o = d_sf + (size_t)(p0 + ty * 2 + m) * 128 + u0;
            o[0] = lo + bb0; o[1] = hi + bb1;
        }
    }
}

// ---------------- global max pool: partial + final ----------------
__global__ void gmax_part() {
    int b = blockIdx.x, s = blockIdx.y, o = threadIdx.x;
    const float* p = d_sf + ((size_t)b * Nn + s * 125) * 128 + o;
    float m0 = -3.4e38f, m1 = -3.4e38f, m2 = -3.4e38f, m3 = -3.4e38f;
    for (int n = 0; n < 124; n += 4) {
        m0 = fmaxf(m0, p[(n + 0) * 128]);
        m1 = fmaxf(m1, p[(n + 1) * 128]);
        m2 = fmaxf(m2, p[(n + 2) * 128]);
        m3 = fmaxf(m3, p[(n + 3) * 128]);
    }
    m0 = fmaxf(m0, p[124 * 128]);
    d_gp[(b * 8 + s) * 128 + o] = fmaxf(fmaxf(m0, m1), fmaxf(m2, m3));
}
__global__ void gmax_fin() {
    int t = threadIdx.x;
    int b = t >> 7, o = t & 127;
    float m = -3.4e38f;
    #pragma unroll
    for (int s = 0; s < 8; s++) m = fmaxf(m, d_gp[(b * 8 + s) * 128 + o]);
    d_g[b * 128 + o] = m;
}

// ---------------- hi/hj projection: 8 points per CTA ----------------
__global__ __launch_bounds__(256) void hij_b(const float* __restrict__ ecw1) {
    __shared__ float st[128][10];
    int t = threadIdx.x;
    int p0 = blockIdx.x * 8;
    for (int idx = t; idx < 8 * 128; idx += 256) {
        int r = idx >> 7, d = idx & 127;
        st[d][r] = d_sf[(size_t)(p0 + r) * 128 + d];
    }
    __syncthreads();
    int col = t & 127, which = t >> 7;
    const float* w = ecw1 + (size_t)which * 128 * 128 + col;
    unsigned long long acc[4] = {0ull, 0ull, 0ull, 0ull};
    for (int d = 0; d < 128; d++) {
        unsigned long long wv = pack2(w[(size_t)d * 128]);
        const unsigned long long* sp = (const unsigned long long*)(&st[d][0]);
        #pragma unroll
        for (int m = 0; m < 4; m++) FFMA2(acc[m], sp[m], wv);
    }
    float* out = which ? d_hj : d_hi;
    #pragma unroll
    for (int m = 0; m < 4; m++) {
        float lo, hi; unpk(acc[m], lo, hi);
        out[(size_t)(p0 + 2 * m) * 128 + col]     = lo;
        out[(size_t)(p0 + 2 * m + 1) * 128 + col] = hi;
    }
}

// ---------------- hg = g @ W[256:] + b1 ----------------
__global__ void hg_kernel(const float* __restrict__ ecw1, const float* __restrict__ ecb1) {
    int t = threadIdx.x;
    int b = t >> 7, o = t & 127;
    float acc = ecb1[o];
    for (int d = 0; d < 128; d++) acc += d_g[b * 128 + d] * ecw1[(256 + d) * 128 + o];
    d_hg[b * 128 + o] = acc;
}

// ---------------- pair scorer: 32x32 tiles, 2x2 register tiling ----------------
#define TILE 32
#define PADC 132
__global__ __launch_bounds__(256) void pair_kernel(
    const float* __restrict__ ecw2, const float* __restrict__ ecb2,
    float* __restrict__ out, int write_logits)
{
    __shared__ __align__(16) float shi[TILE][PADC];
    __shared__ __align__(16) float shj[TILE][PADC];
    __shared__ __align__(16) float shg[128];
    __shared__ __align__(16) float sw2[128];
    int jt = blockIdx.x, it = blockIdx.y, b = blockIdx.z;
    if (jt < it) return;
    int t  = threadIdx.x;
    int i0 = it * TILE, j0 = jt * TILE;
    if (t < 128) { shg[t] = d_hg[b * 128 + t]; sw2[t] = ecw2[t]; }
    __syncthreads();
    for (int idx = t; idx < TILE * 128; idx += 256) {
        int r = idx >> 7, u = idx & 127;
        int gi = i0 + r, gj = j0 + r;
        shi[r][u] = (gi < Nn) ? d_hi[((size_t)b * Nn + gi) * 128 + u] + shg[u] : 0.f;
        shj[r][u] = (gj < Nn) ? d_hj[((size_t)b * Nn + gj) * 128 + u] : 0.f;
    }
    __syncthreads();
    float bias = ecb2[0];
    const long P = (long)Nn * (Nn - 1) / 2;
    int ii = t >> 4;
    int jj = t & 15;
    float a00 = 0.f, a01 = 0.f, a10 = 0.f, a11 = 0.f;
    const float4* vi0 = (const float4*)shi[ii];
    const float4* vi1 = (const float4*)shi[ii + 16];
    const float4* vj0 = (const float4*)shj[jj];
    const float4* vj1 = (const float4*)shj[jj + 16];
    const float4* vw  = (const float4*)sw2;
    #pragma unroll
    for (int q = 0; q < 32; q++) {
        float4 A0 = vi0[q], A1 = vi1[q], B0 = vj0[q], B1 = vj1[q], w = vw[q];
        a00 += fmaxf(A0.x + B0.x, 0.f) * w.x; a00 += fmaxf(A0.y + B0.y, 0.f) * w.y;
        a00 += fmaxf(A0.z + B0.z, 0.f) * w.z; a00 += fmaxf(A0.w + B0.w, 0.f) * w.w;
        a01 += fmaxf(A0.x + B1.x, 0.f) * w.x; a01 += fmaxf(A0.y + B1.y, 0.f) * w.y;
        a01 += fmaxf(A0.z + B1.z, 0.f) * w.z; a01 += fmaxf(A0.w + B1.w, 0.f) * w.w;
        a10 += fmaxf(A1.x + B0.x, 0.f) * w.x; a10 += fmaxf(A1.y + B0.y, 0.f) * w.y;
        a10 += fmaxf(A1.z + B0.z, 0.f) * w.z; a10 += fmaxf(A1.w + B0.w, 0.f) * w.w;
        a11 += fmaxf(A1.x + B1.x, 0.f) * w.x; a11 += fmaxf(A1.y + B1.y, 0.f) * w.y;
        a11 += fmaxf(A1.z + B1.z, 0.f) * w.z; a11 += fmaxf(A1.w + B1.w, 0.f) * w.w;
    }
    float accs[2][2] = {{a00, a01}, {a10, a11}};
    #pragma unroll
    for (int a = 0; a < 2; a++) {
        #pragma unroll
        for (int c = 0; c < 2; c++) {
            int i = i0 + ii + a * 16;
            int j = j0 + jj + c * 16;
            if (i < Nn && j < Nn && i < j) {
                float logit = accs[a][c] + bias;
                long pidx = (long)b * P + (long)i * (2 * Nn - i - 1) / 2 + (j - i - 1);
                out[pidx] = 1.f / (1.f + __expf(-logit));
                if (write_logits) out[(long)Bb * P + pidx] = logit;
            }
        }
    }
}

extern "C" void kernel_launch(void* const* d_in, const int* in_sizes, int n_in,
                              void* d_out, int out_size) {
    const float* pos  = (const float*)d_in[0];
    const float* c1w1 = (const float*)d_in[1];
    const float* c1b1 = (const float*)d_in[2];
    const float* c1w2 = (const float*)d_in[3];
    const float* c1b2 = (const float*)d_in[4];
    const float* c2w1 = (const float*)d_in[5];
    const float* c2b1 = (const float*)d_in[6];
    const float* c2w2 = (const float*)d_in[7];
    const float* c2b2 = (const float*)d_in[8];
    const float* c3w1 = (const float*)d_in[9];
    const float* c3b1 = (const float*)d_in[10];
    const float* c3w2 = (const float*)d_in[11];
    const float* c3b2 = (const float*)d_in[12];
    const float* smw1 = (const float*)d_in[13];
    const float* smb1 = (const float*)d_in[14];
    const float* smw2 = (const float*)d_in[15];
    const float* smb2 = (const float*)d_in[16];
    const float* ecw1 = (const float*)d_in[17];
    const float* ecb1 = (const float*)d_in[18];
    const float* ecw2 = (const float*)d_in[19];
    const float* ecb2 = (const float*)d_in[20];
    float* out = (float*)d_out;

    const long P = (long)Nn * (Nn - 1) / 2;
    int write_logits = ((long)out_size >= 2L * Bb * P) ? 1 : 0;

    float* feat = nullptr;
    cudaGetSymbolAddress((void**)&feat, d_feat);

    // dynamic smem (bytes)
    const int SMP2 = (32 * 20 + 32 * 128) * 4;                  // pregemm ec2: 18,944
    const int SMP3 = (128 * 20 + 32 * 256) * 4;                 // pregemm ec3: 43,008
    const int SME2 = (4 * 64 + 64 * 36 + 32 * 128) * 4;         // ecpre ec2: 26,624
    const int SME3 = (4 * 256 + 256 * 36 + 32 * 256) * 4;       // ecpre ec3: 73,728
    const int SMS  = (FEAT * 20 + 256 * 20 + 32 * 256) * 4;     // sfmlp: 107,008
    cudaFuncSetAttribute(pregemm<32, 64>,   cudaFuncAttributeMaxDynamicSharedMemorySize, SMP2);
    cudaFuncSetAttribute(pregemm<128, 256>, cudaFuncAttributeMaxDynamicSharedMemorySize, SMP3);
    cudaFuncSetAttribute(ecpre<64, 128, 1>,  cudaFuncAttributeMaxDynamicSharedMemorySize, SME2);
    cudaFuncSetAttribute(ecpre<256, 512, 2>, cudaFuncAttributeMaxDynamicSharedMemorySize, SME3);
    cudaFuncSetAttribute(sfmlp_b, cudaFuncAttributeMaxDynamicSharedMemorySize, SMS);

    // stage 1: kNN on pos (C=3), EdgeConv 6->16->32 -> feat[:,0:32]
    knn_b<3><<<250, 256>>>(pos, 3, 0);
    edgeconv1<<<Bb * Nn, 256>>>(pos, c1w1, c1b1, c1w2, c1b2);

    // stage 2: kNN on x1 (C=32); EdgeConv 64->64->128 via pre-GEMM split
    knn_b<32><<<250, 256>>>(feat, FEAT, 0);
    wcomb_kernel<<<(32 * 64 + 255) / 256, 256>>>(c2w1, 32, 64);
    pregemm<32, 64><<<125, 256, SMP2>>>(feat, FEAT, 0);
    ecpre<64, 128, 1><<<500, 128, SME2>>>(32, c2b1, c2w2, c2b2);

    // stage 3: kNN on x2 (C=128); EdgeConv 256->256->512 via pre-GEMM split
    knn_b<128><<<250, 256>>>(feat, FEAT, 32);
    wcomb_kernel<<<(128 * 256 + 255) / 256, 256>>>(c3w1, 128, 256);
    pregemm<128, 256><<<125, 256, SMP3>>>(feat, FEAT, 32);
    ecpre<256, 512, 2><<<500, 256, SME3>>>(160, c3b1, c3w2, c3b2);

    // sf MLP, global max, pair projections
    sfmlp_b<<<125, 256, SMS>>>(smw1, smb1, smw2, smb2);
    dim3 gg(Bb, 8);
    gmax_part<<<gg, 128>>>();
    gmax_fin<<<1, 256>>>();
    hij_b<<<250, 256>>>(ecw1);
    hg_kernel<<<1, 256>>>(ecw1, ecb1);

    // pair scorer
    dim3 pg((Nn + TILE - 1) / TILE, (Nn + TILE - 1) / TILE, Bb);
    pair_kernel<<<pg, 256>>>(ecw2, ecb2, out, write_logits);
}

// round 16
// speedup vs baseline: 1.2130x; 1.0803x over previous
#include <cuda_runtime.h>
#include <math.h>

#define Bb 2
#define Nn 1000
#define KNN 8
#define FEAT 672
#define DPAIR 128

// ---------------- scratch (device globals; no allocation) ----------------
__device__ int   d_knn[Bb * Nn * KNN];
__device__ float d_feat[Bb * Nn * FEAT];    // x1 | x2 | x3 packed at cols 0,32,160
__device__ float d_sf[Bb * Nn * DPAIR];
__device__ float d_gp[Bb * 8 * DPAIR];
__device__ float d_hi[Bb * Nn * DPAIR];
__device__ float d_hj[Bb * Nn * DPAIR];
__device__ float d_hg[Bb * DPAIR];
__device__ float d_vu[Bb * Nn * 512];       // per-point [w | u] rows (ld = 2H)
__device__ float d_wc[256 * 512];           // combined weight [CIN][2H]

// ---------------- f32x2 packed helpers ----------------
__device__ __forceinline__ unsigned long long pack2(float v) {
    unsigned long long r;
    asm("mov.b64 %0, {%1, %1};" : "=l"(r) : "f"(v));
    return r;
}
__device__ __forceinline__ unsigned long long packab(float a, float b) {
    unsigned long long r;
    asm("mov.b64 %0, {%1, %2};" : "=l"(r) : "f"(a), "f"(b));
    return r;
}
#define FFMA2(acc, a, b) asm("fma.rn.f32x2 %0, %1, %2, %0;" : "+l"(acc) : "l"(a), "l"(b))
__device__ __forceinline__ void unpk(unsigned long long v, float& lo, float& hi) {
    asm("mov.b64 {%0, %1}, %2;" : "=f"(lo), "=f"(hi) : "l"(v));
}
__device__ __forceinline__ float hsum2(unsigned long long v) {
    float lo, hi; unpk(v, lo, hi); return lo + hi;
}

// ---------------- kNN batched: 8 points per CTA (+ fused wcomb tail) --------
template <int C>
__global__ __launch_bounds__(256) void knn_b(
    const float* __restrict__ x, int ld, int off,
    const float* __restrict__ wc_w1, int wcCIN, int wcH)
{
    __shared__ float sd2[8][Nn];
    __shared__ float sxi[8][C];
    int t  = threadIdx.x;
    int p0 = blockIdx.x * 8;
    int b  = p0 / Nn;
    for (int idx = t; idx < 8 * C; idx += 256)
        sxi[idx / C][idx % C] = x[(size_t)(p0 + idx / C) * ld + off + (idx % C)];
    __syncthreads();
    const float* xb = x + (size_t)b * Nn * ld + off;
    for (int j = t; j < Nn; j += 256) {
        if (C % 4 == 0) {
            const float4* xp = (const float4*)(xb + (size_t)j * ld);
            unsigned long long acc[8], nrm = 0ull;
            #pragma unroll
            for (int r = 0; r < 8; r++) acc[r] = 0ull;
            #pragma unroll
            for (int c4 = 0; c4 < C / 4; c4++) {
                float4 v = xp[c4];
                unsigned long long v01 = packab(v.x, v.y);
                unsigned long long v23 = packab(v.z, v.w);
                FFMA2(nrm, v01, v01);
                FFMA2(nrm, v23, v23);
                #pragma unroll
                for (int r = 0; r < 8; r++) {
                    const unsigned long long* s = (const unsigned long long*)(sxi[r]);
                    FFMA2(acc[r], v01, s[2 * c4]);
                    FFMA2(acc[r], v23, s[2 * c4 + 1]);
                }
            }
            float sqj = hsum2(nrm);
            #pragma unroll
            for (int r = 0; r < 8; r++)
                sd2[r][j] = fmaf(-2.f, hsum2(acc[r]), sqj);   // sq_i constant per row: dropped
        } else {
            const float* xj = xb + (size_t)j * ld;
            float v0 = xj[0], v1 = xj[1], v2 = xj[2];
            float sqj = v0 * v0 + v1 * v1 + v2 * v2;
            #pragma unroll
            for (int r = 0; r < 8; r++) {
                float dot = sxi[r][0] * v0 + sxi[r][1] * v1 + sxi[r][2] * v2;
                sd2[r][j] = fmaf(-2.f, dot, sqj);
            }
        }
    }
    __syncthreads();
    int w = t >> 5, lane = t & 31;
    float* row = sd2[w];
    for (int k = 0; k < KNN; k++) {
        float bv = 3.4e38f; int bi = Nn;
        for (int j = lane; j < Nn; j += 32) {
            float v = row[j];
            if (v < bv) { bv = v; bi = j; }
        }
        #pragma unroll
        for (int o = 16; o > 0; o >>= 1) {
            float ov = __shfl_down_sync(0xffffffffu, bv, o);
            int   oi = __shfl_down_sync(0xffffffffu, bi, o);
            if (ov < bv || (ov == bv && oi < bi)) { bv = ov; bi = oi; }
        }
        bi = __shfl_sync(0xffffffffu, bi, 0);
        if (lane == 0) { d_knn[(p0 + w) * KNN + k] = bi; row[bi] = 3.4e38f; }
        __syncwarp();
    }
    // fused wcomb: d_wc[c][0:H] = W1t-W1b, [c][H:2H] = W1b  (next stage's weights)
    if (wc_w1) {
        int total = wcCIN * wcH;
        for (int gid = blockIdx.x * 256 + t; gid < total; gid += gridDim.x * 256) {
            int c = gid / wcH, u = gid % wcH;
            float top = wc_w1[c * wcH + u];
            float bot = wc_w1[(wcCIN + c) * wcH + u];
            d_wc[c * 2 * wcH + u]         = top - bot;
            d_wc[c * 2 * wcH + wcH + u]   = bot;
        }
    }
}

// ---------------- generic f32x2 GEMM tile (TM=2), 256 thr, reg-prefetch ------
template <int KK, int NC, int TM, int MP>
__device__ __forceinline__ void gemm_f2(
    const float* __restrict__ At, const float* __restrict__ Wg, int ldw, int col0,
    float* __restrict__ Wt, unsigned long long (&acc)[TM][4], int tx, int ty, int t)
{
    constexpr int P2 = NC / 64;
    constexpr int NF = (32 * NC / 4) / 256;
    float4 pf[NF];
    #pragma unroll
    for (int f = 0; f < NF; f++) {
        int idx = t + f * 256;
        int c = idx / (NC / 4), u4 = idx - c * (NC / 4);
        pf[f] = *(const float4*)(Wg + (size_t)c * ldw + col0 + u4 * 4);
    }
    for (int kb = 0; kb < KK; kb += 32) {
        #pragma unroll
        for (int f = 0; f < NF; f++)
            ((float4*)Wt)[t + f * 256] = pf[f];
        __syncthreads();
        if (kb + 32 < KK) {
            #pragma unroll
            for (int f = 0; f < NF; f++) {
                int idx = t + f * 256;
                int c = idx / (NC / 4), u4 = idx - c * (NC / 4);
                pf[f] = *(const float4*)(Wg + (size_t)(kb + 32 + c) * ldw + col0 + u4 * 4);
            }
        }
        #pragma unroll 4
        for (int c = 0; c < 32; c++) {
            const float* arow = At + (kb + c) * MP + ty * TM;
            float2 a = *(const float2*)(arow);
            unsigned long long ep0 = pack2(a.x), ep1 = pack2(a.y);
            const unsigned long long* wrow = (const unsigned long long*)(Wt + c * NC);
            #pragma unroll
            for (int p = 0; p < P2; p++) {
                unsigned long long wv = wrow[tx + p * 32];
                FFMA2(acc[0][p], ep0, wv);
                FFMA2(acc[1 % TM][p], ep1, wv);
            }
        }
        __syncthreads();
    }
}

// ---------------- pregemm: VU[2000][2H] = x @ d_wc, 16 points per CTA --------
template <int CIN, int HH>
__global__ __launch_bounds__(256) void pregemm(
    const float* __restrict__ x, int ld, int off)
{
    constexpr int MP  = 20;
    constexpr int NC2 = (2 * HH > 256) ? 256 : 2 * HH;
    extern __shared__ float sm[];
    float* Xt = sm;                 // CIN*20
    float* Wt = Xt + CIN * MP;      // 32*NC2
    int t = threadIdx.x, tx = t & 31, ty = t >> 5;
    int p0 = blockIdx.x * 16;
    for (int idx = t; idx < 16 * (CIN / 4); idx += 256) {
        int r = idx & 15, c4 = idx >> 4;
        float4 v = *(const float4*)(x + (size_t)(p0 + r) * ld + off + c4 * 4);
        Xt[(c4 * 4 + 0) * MP + r] = v.x;
        Xt[(c4 * 4 + 1) * MP + r] = v.y;
        Xt[(c4 * 4 + 2) * MP + r] = v.z;
        Xt[(c4 * 4 + 3) * MP + r] = v.w;
    }
    __syncthreads();
    for (int col0 = 0; col0 < 2 * HH; col0 += NC2) {
        unsigned long long acc[2][4];
        #pragma unroll
        for (int m = 0; m < 2; m++)
            #pragma unroll
            for (int p = 0; p < 4; p++) acc[m][p] = 0ull;
        gemm_f2<CIN, NC2, 2, MP>(Xt, d_wc, 2 * HH, col0, Wt, acc, tx, ty, t);
        constexpr int P2 = NC2 / 64;
        #pragma unroll
        for (int p = 0; p < P2; p++) {
            int u0 = tx * 2 + p * 64;
            #pragma unroll
            for (int m = 0; m < 2; m++) {
                float lo, hi; unpk(acc[m][p], lo, hi);
                float* o = d_vu + (size_t)(p0 + ty * 2 + m) * (2 * HH) + col0 + u0;
                o[0] = lo; o[1] = hi;
            }
        }
    }
}

// ---------------- f32x2 GEMM, TM=8 rows/thread, reg-prefetch -----------------
template <int KK, int NC, int MP, int NT, int CG, int PP>
__device__ __forceinline__ void gemm_t8(
    const float* __restrict__ At, const float* __restrict__ Wg, int ldw, int col0,
    float* __restrict__ Wt, unsigned long long (&acc)[8][2], int tx, int rg, int cg, int t)
{
    constexpr int NF = (32 * NC / 4) / NT;
    float4 pf[NF];
    #pragma unroll
    for (int f = 0; f < NF; f++) {
        int idx = t + f * NT;
        int c = idx / (NC / 4), u4 = idx - c * (NC / 4);
        pf[f] = *(const float4*)(Wg + (size_t)c * ldw + col0 + u4 * 4);
    }
    for (int kb = 0; kb < KK; kb += 32) {
        #pragma unroll
        for (int f = 0; f < NF; f++)
            ((float4*)Wt)[t + f * NT] = pf[f];
        __syncthreads();
        if (kb + 32 < KK) {
            #pragma unroll
            for (int f = 0; f < NF; f++) {
                int idx = t + f * NT;
                int c = idx / (NC / 4), u4 = idx - c * (NC / 4);
                pf[f] = *(const float4*)(Wg + (size_t)(kb + 32 + c) * ldw + col0 + u4 * 4);
            }
        }
        #pragma unroll 4
        for (int c = 0; c < 32; c++) {
            const float* ar = At + (kb + c) * MP + rg * 8;
            float4 a0 = *(const float4*)ar;            // broadcast within warp
            float4 a1 = *(const float4*)(ar + 4);
            unsigned long long e0 = pack2(a0.x), e1 = pack2(a0.y);
            unsigned long long e2 = pack2(a0.z), e3 = pack2(a0.w);
            unsigned long long e4 = pack2(a1.x), e5 = pack2(a1.y);
            unsigned long long e6 = pack2(a1.z), e7 = pack2(a1.w);
            const unsigned long long* wr =
                (const unsigned long long*)(Wt + c * NC) + cg * (NC / CG / 2);
            #pragma unroll
            for (int p = 0; p < PP; p++) {
                unsigned long long wv = wr[tx + p * 32];
                FFMA2(acc[0][p], e0, wv);
                FFMA2(acc[1][p], e1, wv);
                FFMA2(acc[2][p], e2, wv);
                FFMA2(acc[3][p], e3, wv);
                FFMA2(acc[4][p], e4, wv);
                FFMA2(acc[5][p], e5, wv);
                FFMA2(acc[6][p], e6, wv);
                FFMA2(acc[7][p], e7, wv);
            }
        }
        __syncthreads();
    }
}

// ---------------- ecpre: Ht = relu(w_i + u_j + b1) gather, GEMM2 + max -------
// 4 points (32 edges) per CTA. NT = 128*CG. warp w: rg = w/CG (point), cg = w%CG.
template <int H, int COUT, int CG>
__global__ __launch_bounds__(128 * CG) void ecpre(
    int off_out,
    const float* __restrict__ b1,
    const float* __restrict__ w2, const float* __restrict__ b2)
{
    constexpr int NT  = 128 * CG;
    constexpr int ED  = 32;
    constexpr int MP  = 36;
    constexpr int NC2 = (COUT > 256) ? 256 : COUT;
    constexpr int PP2 = NC2 / CG / 64;
    extern __shared__ float sm[];
    float* sw = sm;                 // 4*H   (w_i rows)
    float* Ht = sw + 4 * H;         // H*MP
    float* Wt = Ht + H * MP;        // 32*NC2
    __shared__ int sidx[ED];
    int t = threadIdx.x, tx = t & 31, w = t >> 5;
    int rg = w / CG, cg = w % CG;
    int p0 = blockIdx.x * 4;
    int b  = p0 / Nn;
    if (t < ED) sidx[t] = d_knn[p0 * KNN + t];
    for (int idx = t; idx < H; idx += NT) {         // 4 rows of w_i
        #pragma unroll
        for (int p = 0; p < 4; p++)
            sw[p * H + idx] = d_vu[(size_t)(p0 + p) * (2 * H) + idx];
    }
    __syncthreads();
    // build Ht[u][r] = relu(w_i[u] + u_j[u] + b1[u])
    for (int idx = t; idx < ED * (H / 4); idx += NT) {
        int r = idx & 31, c4 = idx >> 5;
        int j = sidx[r];
        float4 uj = *(const float4*)(d_vu + ((size_t)b * Nn + j) * (2 * H) + H + c4 * 4);
        const float* wr = sw + (r >> 3) * H + c4 * 4;
        float4 bv = *(const float4*)(b1 + c4 * 4);
        Ht[(c4 * 4 + 0) * MP + r] = fmaxf(wr[0] + uj.x + bv.x, 0.f);
        Ht[(c4 * 4 + 1) * MP + r] = fmaxf(wr[1] + uj.y + bv.y, 0.f);
        Ht[(c4 * 4 + 2) * MP + r] = fmaxf(wr[2] + uj.z + bv.z, 0.f);
        Ht[(c4 * 4 + 3) * MP + r] = fmaxf(wr[3] + uj.w + bv.w, 0.f);
    }
    __syncthreads();
    // GEMM2 + in-register max over the 8 neighbors (thread's 8 rows = point rg)
    for (int col0 = 0; col0 < COUT; col0 += NC2) {
        unsigned long long acc[8][2];
        #pragma unroll
        for (int m = 0; m < 8; m++) { acc[m][0] = 0ull; acc[m][1] = 0ull; }
        gemm_t8<H, NC2, MP, NT, CG, PP2>(Ht, w2, COUT, col0, Wt, acc, tx, rg, cg, t);
        #pragma unroll
        for (int p = 0; p < PP2; p++) {
            int u0 = col0 + cg * (NC2 / CG) + (tx + p * 32) * 2;
            float m0 = -3.4e38f, m1 = -3.4e38f;
            #pragma unroll
            for (int m = 0; m < 8; m++) {
                float lo, hi; unpk(acc[m][p], lo, hi);
                m0 = fmaxf(m0, lo);
                m1 = fmaxf(m1, hi);
            }
            float* o = d_feat + (size_t)(p0 + rg) * FEAT + off_out + u0;
            o[0] = m0 + b2[u0];
            o[1] = m1 + b2[u0 + 1];
        }
    }
}

// ---------------- EdgeConv stage 1 batched: 8 points/CTA, warp = point -------
__global__ __launch_bounds__(256) void edgeconv1_b(
    const float* __restrict__ x,
    const float* __restrict__ w1, const float* __restrict__ b1,
    const float* __restrict__ w2, const float* __restrict__ b2)
{
    __shared__ float se[8][8][6];
    __shared__ float sh[8][8][16];
    __shared__ float sxi[8][3];
    __shared__ int   sidx[8][8];
    int t = threadIdx.x, w = t >> 5, l = t & 31;
    int p0 = blockIdx.x * 8;
    int row = p0 + w, b = row / Nn;
    if (l < 8) sidx[w][l] = d_knn[row * KNN + l];
    if (l < 3) sxi[w][l] = x[(size_t)row * 3 + l];
    __syncwarp();
    if (l < 24) {
        int k = l / 3, c = l % 3;
        float xj = x[((size_t)b * Nn + sidx[w][k]) * 3 + c];
        se[w][k][c]     = sxi[w][c];
        se[w][k][3 + c] = xj - sxi[w][c];
    }
    __syncwarp();
    #pragma unroll
    for (int r = 0; r < 4; r++) {
        int idx = r * 32 + l;
        int k = idx >> 4, u = idx & 15;
        float a = b1[u];
        #pragma unroll
        for (int c = 0; c < 6; c++) a += se[w][k][c] * w1[c * 16 + u];
        sh[w][k][u] = fmaxf(a, 0.f);
    }
    __syncwarp();
    {
        int o = l;
        float mx = -3.4e38f;
        #pragma unroll
        for (int k = 0; k < KNN; k++) {
            float a = 0.f;
            #pragma unroll
            for (int u = 0; u < 16; u++) a += sh[w][k][u] * w2[u * 32 + o];
            mx = fmaxf(mx, a);
        }
        d_feat[(size_t)row * FEAT + o] = mx + b2[o];
    }
}

// ---------------- sf-MLP batched (16 pts/CTA) + fused hi/hj projection -------
__global__ __launch_bounds__(256) void sfmlp_b(
    const float* __restrict__ w1, const float* __restrict__ b1,
    const float* __restrict__ w2, const float* __restrict__ b2,
    const float* __restrict__ ecw1)
{
    constexpr int MP = 20;
    extern __shared__ float sm[];
    float* Xt = sm;                     // 672*20
    float* Ht = Xt + FEAT * MP;         // 256*20  (later reused as St[128][MP])
    float* Wt = Ht + 256 * MP;          // 32*256
    int t = threadIdx.x, tx = t & 31, ty = t >> 5;
    int p0 = blockIdx.x * 16;
    for (int idx = t; idx < 16 * (FEAT / 4); idx += 256) {
        int r = idx & 15, c4 = idx >> 4;
        float4 v = *(const float4*)(d_feat + (size_t)(p0 + r) * FEAT + c4 * 4);
        Xt[(c4 * 4 + 0) * MP + r] = v.x;
        Xt[(c4 * 4 + 1) * MP + r] = v.y;
        Xt[(c4 * 4 + 2) * MP + r] = v.z;
        Xt[(c4 * 4 + 3) * MP + r] = v.w;
    }
    __syncthreads();
    unsigned long long acc[2][4];
    #pragma unroll
    for (int m = 0; m < 2; m++)
        #pragma unroll
        for (int p = 0; p < 4; p++) acc[m][p] = 0ull;
    gemm_f2<FEAT, 256, 2, MP>(Xt, w1, 256, 0, Wt, acc, tx, ty, t);
    #pragma unroll
    for (int p = 0; p < 4; p++) {
        int u0 = tx * 2 + p * 64;
        float bb0 = b1[u0], bb1 = b1[u0 + 1];
        #pragma unroll
        for (int m = 0; m < 2; m++) {
            float lo, hi; unpk(acc[m][p], lo, hi);
            Ht[u0 * MP + ty * 2 + m]       = fmaxf(lo + bb0, 0.f);
            Ht[(u0 + 1) * MP + ty * 2 + m] = fmaxf(hi + bb1, 0.f);
        }
    }
    __syncthreads();
    #pragma unroll
    for (int m = 0; m < 2; m++)
        #pragma unroll
        for (int p = 0; p < 4; p++) acc[m][p] = 0ull;
    gemm_f2<256, 128, 2, MP>(Ht, w2, 128, 0, Wt, acc, tx, ty, t);
    // epilogue: write sf to global AND into St (reuse Ht region, rows 0..127)
    #pragma unroll
    for (int p = 0; p < 2; p++) {
        int u0 = tx * 2 + p * 64;
        float bb0 = b2[u0], bb1 = b2[u0 + 1];
        #pragma unroll
        for (int m = 0; m < 2; m++) {
            int r = ty * 2 + m;
            float lo, hi; unpk(acc[m][p], lo, hi);
            float v0 = lo + bb0, v1 = hi + bb1;
            float* o = d_sf + (size_t)(p0 + r) * 128 + u0;
            o[0] = v0; o[1] = v1;
            Ht[u0 * MP + r]       = v0;
            Ht[(u0 + 1) * MP + r] = v1;
        }
    }
    __syncthreads();
    // third GEMM: [hi|hj] = sf @ [ecw1[0:128] | ecw1[128:256]]  (K=128, NC=256)
    {
        constexpr int NC = 256;
        constexpr int NF = 8;   // 32*256/4/256
        float4 pf[NF];
        #pragma unroll
        for (int f = 0; f < NF; f++) {
            int idx = t + f * 256;
            int c = idx / 64, u4 = idx - c * 64;
            int g = u4 * 4;
            pf[f] = (g < 128)
                ? *(const float4*)(ecw1 + (size_t)c * 128 + g)
                : *(const float4*)(ecw1 + (size_t)(128 + c) * 128 + (g - 128));
        }
        #pragma unroll
        for (int m = 0; m < 2; m++)
            #pragma unroll
            for (int p = 0; p < 4; p++) acc[m][p] = 0ull;
        for (int kb = 0; kb < 128; kb += 32) {
            #pragma unroll
            for (int f = 0; f < NF; f++)
                ((float4*)Wt)[t + f * 256] = pf[f];
            __syncthreads();
            if (kb + 32 < 128) {
                #pragma unroll
                for (int f = 0; f < NF; f++) {
                    int idx = t + f * 256;
                    int c = idx / 64, u4 = idx - c * 64;
                    int g = u4 * 4;
                    int d = kb + 32 + c;
                    pf[f] = (g < 128)
                        ? *(const float4*)(ecw1 + (size_t)d * 128 + g)
                        : *(const float4*)(ecw1 + (size_t)(128 + d) * 128 + (g - 128));
                }
            }
            #pragma unroll 4
            for (int c = 0; c < 32; c++) {
                const float* arow = Ht + (kb + c) * MP + ty * 2;
                float2 a = *(const float2*)(arow);
                unsigned long long ep0 = pack2(a.x), ep1 = pack2(a.y);
                const unsigned long long* wrow = (const unsigned long long*)(Wt + c * NC);
                #pragma unroll
                for (int p = 0; p < 4; p++) {
                    unsigned long long wv = wrow[tx + p * 32];
                    FFMA2(acc[0][p], ep0, wv);
                    FFMA2(acc[1][p], ep1, wv);
                }
            }
            __syncthreads();
        }
        #pragma unroll
        for (int p = 0; p < 4; p++) {
            int u0 = tx * 2 + p * 64;
            #pragma unroll
            for (int m = 0; m < 2; m++) {
                int r = ty * 2 + m;
                float lo, hi; unpk(acc[m][p], lo, hi);
                if (p < 2) {
                    float* o = d_hi + (size_t)(p0 + r) * 128 + u0;
                    o[0] = lo; o[1] = hi;
                } else {
                    float* o = d_hj + (size_t)(p0 + r) * 128 + (u0 - 128);
                    o[0] = lo; o[1] = hi;
                }
            }
        }
    }
}

// ---------------- global max pool: partial + final (hg fused) ----------------
__global__ void gmax_part() {
    int b = blockIdx.x, s = blockIdx.y, o = threadIdx.x;
    const float* p = d_sf + ((size_t)b * Nn + s * 125) * 128 + o;
    float m0 = -3.4e38f, m1 = -3.4e38f, m2 = -3.4e38f, m3 = -3.4e38f;
    for (int n = 0; n < 124; n += 4) {
        m0 = fmaxf(m0, p[(n + 0) * 128]);
        m1 = fmaxf(m1, p[(n + 1) * 128]);
        m2 = fmaxf(m2, p[(n + 2) * 128]);
        m3 = fmaxf(m3, p[(n + 3) * 128]);
    }
    m0 = fmaxf(m0, p[124 * 128]);
    d_gp[(b * 8 + s) * 128 + o] = fmaxf(fmaxf(m0, m1), fmaxf(m2, m3));
}
__global__ void gmax_fin(const float* __restrict__ ecw1, const float* __restrict__ ecb1) {
    __shared__ float sg[2][128];
    int t = threadIdx.x;
    int b = t >> 7, o = t & 127;
    float m = -3.4e38f;
    #pragma unroll
    for (int s = 0; s < 8; s++) m = fmaxf(m, d_gp[(b * 8 + s) * 128 + o]);
    sg[b][o] = m;
    __syncthreads();
    float acc = ecb1[o];
    for (int d = 0; d < 128; d++) acc += sg[b][d] * ecw1[(256 + d) * 128 + o];
    d_hg[b * 128 + o] = acc;
}

// ---------------- pair scorer: 32x32 tiles, 2x2 register tiling ----------------
#define TILE 32
#define PADC 132
__global__ __launch_bounds__(256) void pair_kernel(
    const float* __restrict__ ecw2, const float* __restrict__ ecb2,
    float* __restrict__ out, int write_logits)
{
    __shared__ __align__(16) float shi[TILE][PADC];
    __shared__ __align__(16) float shj[TILE][PADC];
    __shared__ __align__(16) float shg[128];
    __shared__ __align__(16) float sw2[128];
    int jt = blockIdx.x, it = blockIdx.y, b = blockIdx.z;
    if (jt < it) return;
    int t  = threadIdx.x;
    int i0 = it * TILE, j0 = jt * TILE;
    if (t < 128) { shg[t] = d_hg[b * 128 + t]; sw2[t] = ecw2[t]; }
    __syncthreads();
    for (int idx = t; idx < TILE * 128; idx += 256) {
        int r = idx >> 7, u = idx & 127;
        int gi = i0 + r, gj = j0 + r;
        shi[r][u] = (gi < Nn) ? d_hi[((size_t)b * Nn + gi) * 128 + u] + shg[u] : 0.f;
        shj[r][u] = (gj < Nn) ? d_hj[((size_t)b * Nn + gj) * 128 + u] : 0.f;
    }
    __syncthreads();
    float bias = ecb2[0];
    const long P = (long)Nn * (Nn - 1) / 2;
    int ii = t >> 4;
    int jj = t & 15;
    float a00 = 0.f, a01 = 0.f, a10 = 0.f, a11 = 0.f;
    const float4* vi0 = (const float4*)shi[ii];
    const float4* vi1 = (const float4*)shi[ii + 16];
    const float4* vj0 = (const float4*)shj[jj];
    const float4* vj1 = (const float4*)shj[jj + 16];
    const float4* vw  = (const float4*)sw2;
    #pragma unroll
    for (int q = 0; q < 32; q++) {
        float4 A0 = vi0[q], A1 = vi1[q], B0 = vj0[q], B1 = vj1[q], w = vw[q];
        a00 += fmaxf(A0.x + B0.x, 0.f) * w.x; a00 += fmaxf(A0.y + B0.y, 0.f) * w.y;
        a00 += fmaxf(A0.z + B0.z, 0.f) * w.z; a00 += fmaxf(A0.w + B0.w, 0.f) * w.w;
        a01 += fmaxf(A0.x + B1.x, 0.f) * w.x; a01 += fmaxf(A0.y + B1.y, 0.f) * w.y;
        a01 += fmaxf(A0.z + B1.z, 0.f) * w.z; a01 += fmaxf(A0.w + B1.w, 0.f) * w.w;
        a10 += fmaxf(A1.x + B0.x, 0.f) * w.x; a10 += fmaxf(A1.y + B0.y, 0.f) * w.y;
        a10 += fmaxf(A1.z + B0.z, 0.f) * w.z; a10 += fmaxf(A1.w + B0.w, 0.f) * w.w;
        a11 += fmaxf(A1.x + B1.x, 0.f) * w.x; a11 += fmaxf(A1.y + B1.y, 0.f) * w.y;
        a11 += fmaxf(A1.z + B1.z, 0.f) * w.z; a11 += fmaxf(A1.w + B1.w, 0.f) * w.w;
    }
    float accs[2][2] = {{a00, a01}, {a10, a11}};
    #pragma unroll
    for (int a = 0; a < 2; a++) {
        #pragma unroll
        for (int c = 0; c < 2; c++) {
            int i = i0 + ii + a * 16;
            int j = j0 + jj + c * 16;
            if (i < Nn && j < Nn && i < j) {
                float logit = accs[a][c] + bias;
                long pidx = (long)b * P + (long)i * (2 * Nn - i - 1) / 2 + (j - i - 1);
                out[pidx] = 1.f / (1.f + __expf(-logit));
                if (write_logits) out[(long)Bb * P + pidx] = logit;
            }
        }
    }
}

extern "C" void kernel_launch(void* const* d_in, const int* in_sizes, int n_in,
                              void* d_out, int out_size) {
    const float* pos  = (const float*)d_in[0];
    const float* c1w1 = (const float*)d_in[1];
    const float* c1b1 = (const float*)d_in[2];
    const float* c1w2 = (const float*)d_in[3];
    const float* c1b2 = (const float*)d_in[4];
    const float* c2w1 = (const float*)d_in[5];
    const float* c2b1 = (const float*)d_in[6];
    const float* c2w2 = (const float*)d_in[7];
    const float* c2b2 = (const float*)d_in[8];
    const float* c3w1 = (const float*)d_in[9];
    const float* c3b1 = (const float*)d_in[10];
    const float* c3w2 = (const float*)d_in[11];
    const float* c3b2 = (const float*)d_in[12];
    const float* smw1 = (const float*)d_in[13];
    const float* smb1 = (const float*)d_in[14];
    const float* smw2 = (const float*)d_in[15];
    const float* smb2 = (const float*)d_in[16];
    const float* ecw1 = (const float*)d_in[17];
    const float* ecb1 = (const float*)d_in[18];
    const float* ecw2 = (const float*)d_in[19];
    const float* ecb2 = (const float*)d_in[20];
    float* out = (float*)d_out;

    const long P = (long)Nn * (Nn - 1) / 2;
    int write_logits = ((long)out_size >= 2L * Bb * P) ? 1 : 0;

    float* feat = nullptr;
    cudaGetSymbolAddress((void**)&feat, d_feat);

    // dynamic smem (bytes)
    const int SMP2 = (32 * 20 + 32 * 128) * 4;                  // pregemm ec2
    const int SMP3 = (128 * 20 + 32 * 256) * 4;                 // pregemm ec3
    const int SME2 = (4 * 64 + 64 * 36 + 32 * 128) * 4;         // ecpre ec2
    const int SME3 = (4 * 256 + 256 * 36 + 32 * 256) * 4;       // ecpre ec3
    const int SMS  = (FEAT * 20 + 256 * 20 + 32 * 256) * 4;     // sfmlp
    cudaFuncSetAttribute(pregemm<32, 64>,   cudaFuncAttributeMaxDynamicSharedMemorySize, SMP2);
    cudaFuncSetAttribute(pregemm<128, 256>, cudaFuncAttributeMaxDynamicSharedMemorySize, SMP3);
    cudaFuncSetAttribute(ecpre<64, 128, 1>,  cudaFuncAttributeMaxDynamicSharedMemorySize, SME2);
    cudaFuncSetAttribute(ecpre<256, 512, 2>, cudaFuncAttributeMaxDynamicSharedMemorySize, SME3);
    cudaFuncSetAttribute(sfmlp_b, cudaFuncAttributeMaxDynamicSharedMemorySize, SMS);

    // stage 1: kNN on pos (C=3), EdgeConv 6->16->32 -> feat[:,0:32]
    knn_b<3><<<250, 256>>>(pos, 3, 0, nullptr, 0, 0);
    edgeconv1_b<<<250, 256>>>(pos, c1w1, c1b1, c1w2, c1b2);

    // stage 2: kNN on x1 (C=32, + wcomb for ec2); EdgeConv 64->64->128 split
    knn_b<32><<<250, 256>>>(feat, FEAT, 0, c2w1, 32, 64);
    pregemm<32, 64><<<125, 256, SMP2>>>(feat, FEAT, 0);
    ecpre<64, 128, 1><<<500, 128, SME2>>>(32, c2b1, c2w2, c2b2);

    // stage 3: kNN on x2 (C=128, + wcomb for ec3); EdgeConv 256->256->512 split
    knn_b<128><<<250, 256>>>(feat, FEAT, 32, c3w1, 128, 256);
    pregemm<128, 256><<<125, 256, SMP3>>>(feat, FEAT, 32);
    ecpre<256, 512, 2><<<500, 256, SME3>>>(160, c3b1, c3w2, c3b2);

    // sf MLP (+ hi/hj), global max (+ hg)
    sfmlp_b<<<125, 256, SMS>>>(smw1, smb1, smw2, smb2, ecw1);
    dim3 gg(Bb, 8);
    gmax_part<<<gg, 128>>>();
    gmax_fin<<<1, 256>>>(ecw1, ecb1);

    // pair scorer
    dim3 pg((Nn + TILE - 1) / TILE, (Nn + TILE - 1) / TILE, Bb);
    pair_kernel<<<pg, 256>>>(ecw2, ecb2, out, write_logits);
}